// round 10
// baseline (speedup 1.0000x reference)
#include <cuda_runtime.h>
#include <math.h>
#include <stdint.h>

// Problem constants
#define Bsz 16
#define Lsz 2048
#define BLn (Bsz*Lsz)          // 32768 (b,l) positions
#define DI 256                 // d_inner
#define DS 16                  // d_state
#define NCH 32                 // scan chunks
#define CLEN (Lsz/NCH)         // 64 steps per chunk

// ---------------- scratch (static device globals; no allocation) ----------------
static __device__ float  g_gate [BLn*DI];   // silu(z)
static __device__ float  g_xc   [BLn*DI];   // silu(conv(x))
static __device__ float2 g_dxc  [BLn*DI];   // packed {delta, xc} from K3
static __device__ float  g_Bm   [BLn*DS];
static __device__ float  g_Cm   [BLn*DS];
static __device__ float  g_P    [Bsz*DI*NCH*DS];  // chunk cum-prod of dA
static __device__ float  g_hl   [Bsz*DI*NCH*DS];  // chunk-local h (h_in = 0)
static __device__ float  g_S    [Bsz*DI*NCH*DS];  // sum_t g*C*cumA
static __device__ float  g_accl [Bsz*DI*NCH];     // chunk-local gated y accum (incl. D term)

__device__ __forceinline__ float silu_f(float x){ return x / (1.0f + __expf(-x)); }
__device__ __forceinline__ float softplus_f(float x){ return (x > 20.0f) ? x : log1pf(__expf(x)); }
__device__ __forceinline__ float to_tf32(float x){
    uint32_t u; asm("cvt.rna.tf32.f32 %0, %1;" : "=r"(u) : "f"(x));
    return __uint_as_float(u);
}

// ---------------- K1: embedding gather + in_proj GEMM (tf32 mma) + FUSED depthwise conv ----------------
// out[m,n] = sum_k emb[ids[m],k] * W[n,k];  M=32768, N=512, K=128.
// Block 256 thr (8 warps), tile BM=128 x BN=64, two K-passes of 64.
// x-half blocks (n0<256): stage RAW tile + 3 halo rows in smem, apply causal conv
//   (D_CONV=4) + bias + SiLU in the epilogue, write g_xc directly (K2 eliminated).
// z-half blocks: SiLU and write g_gate.
__global__ void __launch_bounds__(256) k1_inproj(const int* __restrict__ ids,
                                                 const float* __restrict__ emb,
                                                 const float* __restrict__ wproj,
                                                 const float* __restrict__ conv_w,
                                                 const float* __restrict__ conv_b)
{
    __shared__ __align__(16) float smem_all[12288];   // 48 KB
    float* sA = smem_all;           // 8*8*32*4 = 8192 floats (32 KB)
    float* sW = smem_all + 8192;    // 8*8*32*2 = 4096 floats (16 KB)

    const int tid   = threadIdx.x;
    const int lane  = tid & 31;
    const int w     = tid >> 5;
    const int warpM = w >> 1;       // 0..3  (32 rows each)
    const int warpN = w & 1;        // 0..1  (32 cols each)
    const int m0 = blockIdx.x * 128;
    const int n0 = blockIdx.y * 64;
    const int l0 = m0 & (Lsz - 1);  // 0 or >=128 (tiles never straddle batches)

    int rid[8];
#pragma unroll
    for (int i = 0; i < 8; i++) rid[i] = ids[m0 + i * 16 + (tid >> 4)];

    float acc[2][4][4];
#pragma unroll
    for (int mt = 0; mt < 2; mt++)
#pragma unroll
        for (int nt = 0; nt < 4; nt++)
#pragma unroll
            for (int r = 0; r < 4; r++) acc[mt][nt][r] = 0.0f;

#pragma unroll 1
    for (int pass = 0; pass < 2; pass++){
        const int k0 = pass * 64;

        // ---- fill A: 128 rows x 64 k (tf32), fragment-permuted ----
        {
            const int kq4 = tid & 15;
#pragma unroll
            for (int i = 0; i < 8; i++){
                int row = i * 16 + (tid >> 4);
                float4 v = *(const float4*)(emb + rid[i] * 128 + k0 + kq4 * 4);
                int base = (((row >> 4) * 8 + (kq4 >> 1)) * 32 + (row & 7) * 4) * 4
                           + ((row >> 3) & 1) + 2 * (kq4 & 1);
                sA[base + 0*4] = to_tf32(v.x);
                sA[base + 1*4] = to_tf32(v.y);
                sA[base + 2*4] = to_tf32(v.z);
                sA[base + 3*4] = to_tf32(v.w);
            }
        }
        // ---- fill W: 64 rows x 64 k (tf32), fragment-permuted ----
        {
#pragma unroll
            for (int i = 0; i < 4; i++){
                int idx = i * 256 + tid;         // 0..1023
                int n   = idx >> 4;              // 0..63
                int kq4 = idx & 15;
                float4 v = *(const float4*)(wproj + (n0 + n) * 128 + k0 + kq4 * 4);
                int base = (((n >> 3) * 8 + (kq4 >> 1)) * 32 + (n & 7) * 4) * 2 + (kq4 & 1);
                sW[base + 0*2] = to_tf32(v.x);
                sW[base + 1*2] = to_tf32(v.y);
                sW[base + 2*2] = to_tf32(v.z);
                sW[base + 3*2] = to_tf32(v.w);
            }
        }
        __syncthreads();

#pragma unroll
        for (int k8 = 0; k8 < 8; k8++){
            float4 af[2];
#pragma unroll
            for (int mt = 0; mt < 2; mt++)
                af[mt] = *(const float4*)&sA[(((warpM * 2 + mt) * 8 + k8) * 32 + lane) * 4];
            float2 bf[4];
#pragma unroll
            for (int nt = 0; nt < 4; nt++)
                bf[nt] = *(const float2*)&sW[(((warpN * 4 + nt) * 8 + k8) * 32 + lane) * 2];
#pragma unroll
            for (int mt = 0; mt < 2; mt++)
#pragma unroll
                for (int nt = 0; nt < 4; nt++){
                    asm volatile(
                        "mma.sync.aligned.m16n8k8.row.col.f32.tf32.tf32.f32 "
                        "{%0,%1,%2,%3},{%4,%5,%6,%7},{%8,%9},{%0,%1,%2,%3};"
                        : "+f"(acc[mt][nt][0]), "+f"(acc[mt][nt][1]),
                          "+f"(acc[mt][nt][2]), "+f"(acc[mt][nt][3])
                        : "r"(__float_as_uint(af[mt].x)), "r"(__float_as_uint(af[mt].y)),
                          "r"(__float_as_uint(af[mt].z)), "r"(__float_as_uint(af[mt].w)),
                          "r"(__float_as_uint(bf[nt].x)), "r"(__float_as_uint(bf[nt].y)));
                }
        }
        __syncthreads();
    }

    const bool is_x = (n0 < 256);
    float* sE = smem_all;                // reuse; up to 131 rows x stride 72

    if (is_x){
        // ---- stage RAW tile at rows 3..130 ----
#pragma unroll
        for (int mt = 0; mt < 2; mt++)
#pragma unroll
            for (int nt = 0; nt < 4; nt++)
#pragma unroll
                for (int rh = 0; rh < 2; rh++){
                    int ml = warpM * 32 + mt * 16 + (lane >> 2) + rh * 8;
                    int nl = warpN * 32 + nt * 8 + (lane & 3) * 2;
                    *(float2*)&sE[(ml + 3) * 72 + nl] =
                        make_float2(acc[mt][nt][rh * 2 + 0], acc[mt][nt][rh * 2 + 1]);
                }
        // ---- halo rows 0..2: xcraw(m0-3..m0-1, n0..n0+63) via SIMT dot products ----
        if (tid < 192){
            int r  = tid >> 6;          // 0..2
            int ch = tid & 63;
            float s = 0.0f;
            if (l0 != 0){
                const float4* er = (const float4*)(emb + ids[m0 - 3 + r] * 128);
                const float4* wr = (const float4*)(wproj + (n0 + ch) * 128);
#pragma unroll 8
                for (int kk = 0; kk < 32; kk++){
                    float4 e4 = er[kk], w4 = wr[kk];
                    s = fmaf(e4.x, w4.x, s); s = fmaf(e4.y, w4.y, s);
                    s = fmaf(e4.z, w4.z, s); s = fmaf(e4.w, w4.w, s);
                }
            }
            sE[r * 72 + ch] = s;
        }
        __syncthreads();

        // ---- conv + bias + SiLU + store (each thread owns 4 fixed channels) ----
        const int q  = tid & 15;                // channel quad (invariant over i)
        const int dch = n0 + q * 4;
        float cw[4][4];
#pragma unroll
        for (int cqi = 0; cqi < 4; cqi++){
            float4 wq = __ldg((const float4*)(conv_w + (dch + cqi) * 4));
            cw[cqi][0] = wq.x; cw[cqi][1] = wq.y; cw[cqi][2] = wq.z; cw[cqi][3] = wq.w;
        }
        float4 bb = __ldg((const float4*)(conv_b + dch));
#pragma unroll
        for (int i = 0; i < 8; i++){
            int row = i * 16 + (tid >> 4);      // 0..127
            float4 x0 = *(const float4*)&sE[(row + 0) * 72 + q * 4];  // l-3
            float4 x1 = *(const float4*)&sE[(row + 1) * 72 + q * 4];  // l-2
            float4 x2 = *(const float4*)&sE[(row + 2) * 72 + q * 4];  // l-1
            float4 x3 = *(const float4*)&sE[(row + 3) * 72 + q * 4];  // l
            float a0 = bb.x, a1 = bb.y, a2 = bb.z, a3 = bb.w;
            a0 = fmaf(cw[0][0], x0.x, a0); a1 = fmaf(cw[1][0], x0.y, a1);
            a2 = fmaf(cw[2][0], x0.z, a2); a3 = fmaf(cw[3][0], x0.w, a3);
            a0 = fmaf(cw[0][1], x1.x, a0); a1 = fmaf(cw[1][1], x1.y, a1);
            a2 = fmaf(cw[2][1], x1.z, a2); a3 = fmaf(cw[3][1], x1.w, a3);
            a0 = fmaf(cw[0][2], x2.x, a0); a1 = fmaf(cw[1][2], x2.y, a1);
            a2 = fmaf(cw[2][2], x2.z, a2); a3 = fmaf(cw[3][2], x2.w, a3);
            a0 = fmaf(cw[0][3], x3.x, a0); a1 = fmaf(cw[1][3], x3.y, a1);
            a2 = fmaf(cw[2][3], x3.z, a2); a3 = fmaf(cw[3][3], x3.w, a3);
            float4 o;
            o.x = silu_f(a0); o.y = silu_f(a1); o.z = silu_f(a2); o.w = silu_f(a3);
            *(float4*)(g_xc + (m0 + row) * 256 + dch) = o;
        }
    } else {
        // ---- z half: SiLU, stage, coalesced store to g_gate ----
#pragma unroll
        for (int mt = 0; mt < 2; mt++)
#pragma unroll
            for (int nt = 0; nt < 4; nt++)
#pragma unroll
                for (int rh = 0; rh < 2; rh++){
                    int ml = warpM * 32 + mt * 16 + (lane >> 2) + rh * 8;
                    int nl = warpN * 32 + nt * 8 + (lane & 3) * 2;
                    *(float2*)&sE[ml * 72 + nl] =
                        make_float2(silu_f(acc[mt][nt][rh * 2 + 0]),
                                    silu_f(acc[mt][nt][rh * 2 + 1]));
                }
        __syncthreads();
        const int ncol0 = n0 - 256;
#pragma unroll
        for (int i = 0; i < 8; i++){
            int idx = i * 256 + tid;         // 0..2047
            int row = idx >> 4;
            int q   = idx & 15;
            float4 v = *(const float4*)&sE[row * 72 + q * 4];
            *(float4*)(g_gate + (m0 + row) * 256 + ncol0 + q * 4) = v;
        }
    }
}

// ---------------- K3: x_proj (40x256) + dt_proj (256x8) + softplus; emit {delta,xc}/B/C ----------------
__global__ void __launch_bounds__(256) k3_xproj(const float* __restrict__ xpw,
                                                const float* __restrict__ dtw,
                                                const float* __restrict__ dtb)
{
    __shared__ __align__(16) float sw[40 * 256];
    __shared__ float sdbc[8][4][40];
    const int tid  = threadIdx.x;
    const int lane = tid & 31;
    const int wp   = tid >> 5;
    const int bl0  = (blockIdx.x * 8 + wp) * 4;

#pragma unroll
    for (int i = 0; i < 10; i++)
        ((float4*)sw)[i * 256 + tid] = ((const float4*)xpw)[i * 256 + tid];
    __syncthreads();

    float xcl[4][8];
#pragma unroll
    for (int p = 0; p < 4; p++)
#pragma unroll
        for (int k = 0; k < 8; k++)
            xcl[p][k] = g_xc[(bl0 + p) * 256 + k * 32 + lane];

#pragma unroll 8
    for (int j = 0; j < 40; j++){
        float wl[8];
#pragma unroll
        for (int k = 0; k < 8; k++) wl[k] = sw[j * 256 + k * 32 + lane];
        float s0 = 0.f, s1 = 0.f, s2 = 0.f, s3 = 0.f;
#pragma unroll
        for (int k = 0; k < 8; k++){
            s0 = fmaf(wl[k], xcl[0][k], s0);
            s1 = fmaf(wl[k], xcl[1][k], s1);
            s2 = fmaf(wl[k], xcl[2][k], s2);
            s3 = fmaf(wl[k], xcl[3][k], s3);
        }
#pragma unroll
        for (int off = 16; off; off >>= 1){
            s0 += __shfl_xor_sync(0xffffffffu, s0, off);
            s1 += __shfl_xor_sync(0xffffffffu, s1, off);
            s2 += __shfl_xor_sync(0xffffffffu, s2, off);
            s3 += __shfl_xor_sync(0xffffffffu, s3, off);
        }
        if (lane == 0){
            sdbc[wp][0][j] = s0; sdbc[wp][1][j] = s1;
            sdbc[wp][2][j] = s2; sdbc[wp][3][j] = s3;
        }
    }
    __syncwarp();

    if (lane < 16){
#pragma unroll
        for (int p = 0; p < 4; p++){
            g_Bm[(bl0 + p) * 16 + lane] = sdbc[wp][p][8  + lane];
            g_Cm[(bl0 + p) * 16 + lane] = sdbc[wp][p][24 + lane];
        }
    }

#pragma unroll
    for (int k = 0; k < 8; k++){
        int d = k * 32 + lane;
        float4 w0 = __ldg((const float4*)(dtw + d * 8));
        float4 w1 = __ldg((const float4*)(dtw + d * 8 + 4));
        float bias = __ldg(dtb + d);
#pragma unroll
        for (int p = 0; p < 4; p++){
            const float* dv = sdbc[wp][p];
            float t = bias;
            t = fmaf(w0.x, dv[0], t); t = fmaf(w0.y, dv[1], t);
            t = fmaf(w0.z, dv[2], t); t = fmaf(w0.w, dv[3], t);
            t = fmaf(w1.x, dv[4], t); t = fmaf(w1.y, dv[5], t);
            t = fmaf(w1.z, dv[6], t); t = fmaf(w1.w, dv[7], t);
            g_dxc[(bl0 + p) * 256 + d] = make_float2(softplus_f(t), xcl[p][k]);
        }
    }
}

// ---------------- K4: chunked selective scan, pass A ----------------
// Warp-half sh: tid<128 -> states 0..7, tid>=128 -> states 8..15 of channel d=tid&127.
// In-kernel exp (e1 per 4-step batch) and D-term; merged gC = gv*C gating.
// Cross-half combine via one smem word.
__global__ void __launch_bounds__(256, 3) k4_scan(const float* __restrict__ A_log,
                                                  const float* __restrict__ Dvec)
{
    __shared__ __align__(16) float sB[CLEN * 16];
    __shared__ __align__(16) float sC[CLEN * 16];
    __shared__ float sacc[128];

    const int b   = blockIdx.x >> 6;         // 32 chunks * 2 channel-halves
    const int c   = (blockIdx.x >> 1) & 31;
    const int hb  = blockIdx.x & 1;          // channel-half block
    const int tid = threadIdx.x;
    const int sh  = tid >> 7;                // state half (warp-uniform)
    const int dl  = tid & 127;
    const int d   = hb * 128 + dl;
    const int n0  = sh * 8;

    const float An0 = -__expf(__ldg(A_log + d * 16));
    bool pw_ok = true;
#pragma unroll
    for (int j = 0; j < 8; j++){
        float Ann = -__expf(__ldg(A_log + d * 16 + n0 + j));
        pw_ok = pw_ok && (fabsf(Ann / An0 - (float)(n0 + j + 1)) < 1e-3f);
    }
    const float Dd_eff = sh ? 0.0f : __ldg(Dvec + d);   // only half 0 adds the D term

    const int l0 = b * Lsz + c * CLEN;
    {
        const float4* gB = (const float4*)(g_Bm + l0 * 16);
        const float4* gC4 = (const float4*)(g_Cm + l0 * 16);
        ((float4*)sB)[tid] = gB[tid];
        ((float4*)sC)[tid] = gC4[tid];
    }
    __syncthreads();

    float h[8], P[8], S[8];
#pragma unroll
    for (int j = 0; j < 8; j++){ h[j] = 0.0f; P[j] = 1.0f; S[j] = 0.0f; }
    float accl = 0.0f;

    int base = l0 * 256 + d;

    if (pw_ok){
        float2 pdx[4]; float pg[4];
#pragma unroll
        for (int q = 0; q < 4; q++){
            pdx[q] = g_dxc[base + q * 256];
            pg[q]  = __ldg(g_gate + base + q * 256);
        }
#pragma unroll 1
        for (int t = 0; t < CLEN; t += 4){
            float2 cdx[4]; float cg[4];
#pragma unroll
            for (int q = 0; q < 4; q++){ cdx[q] = pdx[q]; cg[q] = pg[q]; }
            int nb = base + 4 * 256;
            if (t + 4 < CLEN){
#pragma unroll
                for (int q = 0; q < 4; q++){
                    pdx[q] = g_dxc[nb + q * 256];
                    pg[q]  = __ldg(g_gate + nb + q * 256);
                }
            }
            float e1v[4];
#pragma unroll
            for (int q = 0; q < 4; q++) e1v[q] = __expf(cdx[q].x * An0);

#pragma unroll
            for (int q = 0; q < 4; q++){
                float gv  = cg[q];
                float xcv = cdx[q].y;
                float dxv = cdx[q].x * xcv;

                // powers e1^1..e1^8; upper half shifts by e1^8 (warp-uniform)
                float qp[8];
                qp[0] = e1v[q];
#pragma unroll
                for (int i = 1; i < 8; i++) qp[i] = qp[(i - 1) >> 1] * qp[i >> 1];
                if (sh){
                    float e8 = qp[7];
#pragma unroll
                    for (int j = 0; j < 8; j++) qp[j] *= e8;
                }

                float4 bb0 = ((const float4*)sB)[(t + q) * 4 + sh * 2 + 0];
                float4 bb1 = ((const float4*)sB)[(t + q) * 4 + sh * 2 + 1];
                float4 cc0 = ((const float4*)sC)[(t + q) * 4 + sh * 2 + 0];
                float4 cc1 = ((const float4*)sC)[(t + q) * 4 + sh * 2 + 1];
                float Bv[8] = {bb0.x, bb0.y, bb0.z, bb0.w, bb1.x, bb1.y, bb1.z, bb1.w};
                float gC[8] = {gv*cc0.x, gv*cc0.y, gv*cc0.z, gv*cc0.w,
                               gv*cc1.x, gv*cc1.y, gv*cc1.z, gv*cc1.w};

#pragma unroll
                for (int j = 0; j < 8; j++){
                    P[j] *= qp[j];
                    h[j] = fmaf(qp[j], h[j], dxv * Bv[j]);
                    accl = fmaf(h[j], gC[j], accl);
                    S[j] = fmaf(P[j], gC[j], S[j]);
                }
                accl = fmaf(gv * xcv, Dd_eff, accl);
            }
            base = nb;
        }
    } else {
        // cold generic path (correctness only)
#pragma unroll 1
        for (int t = 0; t < CLEN; t++){
            float2 dxc  = g_dxc[base];
            float delta = dxc.x;
            float xcv   = dxc.y;
            float gv    = g_gate[base];
            float dxv   = delta * xcv;
#pragma unroll 4
            for (int j = 0; j < 8; j++){
                float An = -__expf(__ldg(A_log + d * 16 + n0 + j));
                float dA = __expf(delta * An);
                float Bn = sB[t * 16 + n0 + j];
                float Cn = sC[t * 16 + n0 + j] * gv;
                P[j] *= dA;
                h[j] = fmaf(dA, h[j], dxv * Bn);
                accl = fmaf(h[j], Cn, accl);
                S[j] = fmaf(P[j], Cn, S[j]);
            }
            accl = fmaf(gv * xcv, Dd_eff, accl);
            base += 256;
        }
    }

    // cross-half combine (one smem word per channel)
    if (sh) sacc[dl] = accl;
    __syncthreads();

    const int ob = (b * 256 + d) * NCH + c;
    if (!sh) g_accl[ob] = accl + sacc[dl];
    *(float4*)(g_P  + ob * 16 + n0)     = make_float4(P[0], P[1], P[2], P[3]);
    *(float4*)(g_P  + ob * 16 + n0 + 4) = make_float4(P[4], P[5], P[6], P[7]);
    *(float4*)(g_hl + ob * 16 + n0)     = make_float4(h[0], h[1], h[2], h[3]);
    *(float4*)(g_hl + ob * 16 + n0 + 4) = make_float4(h[4], h[5], h[6], h[7]);
    *(float4*)(g_S  + ob * 16 + n0)     = make_float4(S[0], S[1], S[2], S[3]);
    *(float4*)(g_S  + ob * 16 + n0 + 4) = make_float4(S[4], S[5], S[6], S[7]);
}

// ---------------- K5: chunk combine + out_proj + mean + classifier (merged tail) ----------------
// One block per batch b (256 threads, one per channel d).
__global__ void __launch_bounds__(256) k5_tail(const float* __restrict__ opw,
                                               const float* __restrict__ clw,
                                               const float* __restrict__ clb,
                                               float* __restrict__ out)
{
    __shared__ float sacc[256];
    __shared__ float mvec[128];
    const int b   = blockIdx.x;
    const int tid = threadIdx.x;
    const int gid = b * 256 + tid;

    float h[16];
#pragma unroll
    for (int n = 0; n < 16; n++) h[n] = 0.0f;
    float acc = 0.0f;
#pragma unroll 1
    for (int c = 0; c < NCH; c++){
        int base = gid * NCH + c;
        acc += g_accl[base];
        const float4* sp = (const float4*)(g_S  + base * 16);
        const float4* pp = (const float4*)(g_P  + base * 16);
        const float4* hp = (const float4*)(g_hl + base * 16);
#pragma unroll
        for (int q = 0; q < 4; q++){
            float4 sv = sp[q], pv = pp[q], hv = hp[q];
            acc = fmaf(h[q*4+0], sv.x, acc);
            acc = fmaf(h[q*4+1], sv.y, acc);
            acc = fmaf(h[q*4+2], sv.z, acc);
            acc = fmaf(h[q*4+3], sv.w, acc);
            h[q*4+0] = fmaf(pv.x, h[q*4+0], hv.x);
            h[q*4+1] = fmaf(pv.y, h[q*4+1], hv.y);
            h[q*4+2] = fmaf(pv.z, h[q*4+2], hv.z);
            h[q*4+3] = fmaf(pv.w, h[q*4+3], hv.w);
        }
    }
    sacc[tid] = acc;
    __syncthreads();

    if (tid < 128){
        float s = 0.0f;
#pragma unroll 8
        for (int e = 0; e < 256; e++) s = fmaf(sacc[e], __ldg(opw + tid * 256 + e), s);
        mvec[tid] = s * (1.0f / 2048.0f);
    }
    __syncthreads();
    if (tid < 2){
        float t = __ldg(clb + tid);
#pragma unroll 8
        for (int e = 0; e < 128; e++) t = fmaf(mvec[e], __ldg(clw + tid * 128 + e), t);
        out[b * 2 + tid] = t;
    }
}

// ---------------- launch ----------------
extern "C" void kernel_launch(void* const* d_in, const int* in_sizes, int n_in,
                              void* d_out, int out_size)
{
    const int*   ids  = (const int*)  d_in[0];
    const float* emb  = (const float*)d_in[1];
    const float* ipw  = (const float*)d_in[2];
    const float* cw   = (const float*)d_in[3];
    const float* cb   = (const float*)d_in[4];
    const float* xpw  = (const float*)d_in[5];
    const float* dtw  = (const float*)d_in[6];
    const float* dtb  = (const float*)d_in[7];
    const float* alog = (const float*)d_in[8];
    const float* dvec = (const float*)d_in[9];
    const float* opw  = (const float*)d_in[10];
    const float* clw  = (const float*)d_in[11];
    const float* clb  = (const float*)d_in[12];
    float* out = (float*)d_out;

    dim3 g1(BLn / 128, 8);   // 256 m-tiles x 8 n-tiles of 64
    k1_inproj<<<g1, 256>>>(ids, emb, ipw, cw, cb);
    k3_xproj<<<BLn / 32, 256>>>(xpw, dtw, dtb);
    k4_scan<<<Bsz * NCH * 2, 256>>>(alog, dvec);
    k5_tail<<<Bsz, 256>>>(opw, clw, clb, out);
}

// round 11
// speedup vs baseline: 1.0849x; 1.0849x over previous
#include <cuda_runtime.h>
#include <math.h>
#include <stdint.h>

// Problem constants
#define Bsz 16
#define Lsz 2048
#define BLn (Bsz*Lsz)          // 32768 (b,l) positions
#define DI 256                 // d_inner
#define DS 16                  // d_state
#define NCH 32                 // scan chunks
#define CLEN (Lsz/NCH)         // 64 steps per chunk

// ---------------- scratch (static device globals; no allocation) ----------------
static __device__ float  g_gate [BLn*DI];   // silu(z)
static __device__ float  g_xc   [BLn*DI];   // silu(conv(x))
static __device__ float2 g_dxc  [BLn*DI];   // packed {delta, xc} from K3
static __device__ float  g_Bm   [BLn*DS];
static __device__ float  g_Cm   [BLn*DS];
// chunk state, channel-fastest float4 quads: [((b*NCH+c)*4+q)*DI + d]
static __device__ float4 g_P4 [Bsz*NCH*4*DI];
static __device__ float4 g_h4 [Bsz*NCH*4*DI];
static __device__ float4 g_S4 [Bsz*NCH*4*DI];
static __device__ float  g_accl[Bsz*NCH*DI];     // [(b*NCH+c)*DI + d]

__device__ __forceinline__ float silu_f(float x){ return x / (1.0f + __expf(-x)); }
__device__ __forceinline__ float softplus_f(float x){ return (x > 20.0f) ? x : log1pf(__expf(x)); }
__device__ __forceinline__ float to_tf32(float x){
    uint32_t u; asm("cvt.rna.tf32.f32 %0, %1;" : "=r"(u) : "f"(x));
    return __uint_as_float(u);
}

// ---------------- K1: embedding gather + in_proj GEMM (tf32 mma) + FUSED depthwise conv ----------------
// out[m,n] = sum_k emb[ids[m],k] * W[n,k];  M=32768, N=512, K=128.
// Block 256 thr (8 warps), tile BM=128 x BN=64, two K-passes of 64.
// x-half blocks (n0<256): stage RAW tile + 3 halo rows in smem, apply causal conv
//   (D_CONV=4) + bias + SiLU in the epilogue, write g_xc directly.
// z-half blocks: SiLU and write g_gate.
__global__ void __launch_bounds__(256) k1_inproj(const int* __restrict__ ids,
                                                 const float* __restrict__ emb,
                                                 const float* __restrict__ wproj,
                                                 const float* __restrict__ conv_w,
                                                 const float* __restrict__ conv_b)
{
    __shared__ __align__(16) float smem_all[12288];   // 48 KB
    float* sA = smem_all;           // 8*8*32*4 = 8192 floats (32 KB)
    float* sW = smem_all + 8192;    // 8*8*32*2 = 4096 floats (16 KB)

    const int tid   = threadIdx.x;
    const int lane  = tid & 31;
    const int w     = tid >> 5;
    const int warpM = w >> 1;       // 0..3  (32 rows each)
    const int warpN = w & 1;        // 0..1  (32 cols each)
    const int m0 = blockIdx.x * 128;
    const int n0 = blockIdx.y * 64;
    const int l0 = m0 & (Lsz - 1);  // 0 or >=128 (tiles never straddle batches)

    int rid[8];
#pragma unroll
    for (int i = 0; i < 8; i++) rid[i] = ids[m0 + i * 16 + (tid >> 4)];

    float acc[2][4][4];
#pragma unroll
    for (int mt = 0; mt < 2; mt++)
#pragma unroll
        for (int nt = 0; nt < 4; nt++)
#pragma unroll
            for (int r = 0; r < 4; r++) acc[mt][nt][r] = 0.0f;

#pragma unroll 1
    for (int pass = 0; pass < 2; pass++){
        const int k0 = pass * 64;

        // ---- fill A: 128 rows x 64 k (tf32), fragment-permuted ----
        {
            const int kq4 = tid & 15;
#pragma unroll
            for (int i = 0; i < 8; i++){
                int row = i * 16 + (tid >> 4);
                float4 v = *(const float4*)(emb + rid[i] * 128 + k0 + kq4 * 4);
                int base = (((row >> 4) * 8 + (kq4 >> 1)) * 32 + (row & 7) * 4) * 4
                           + ((row >> 3) & 1) + 2 * (kq4 & 1);
                sA[base + 0*4] = to_tf32(v.x);
                sA[base + 1*4] = to_tf32(v.y);
                sA[base + 2*4] = to_tf32(v.z);
                sA[base + 3*4] = to_tf32(v.w);
            }
        }
        // ---- fill W: 64 rows x 64 k (tf32), fragment-permuted ----
        {
#pragma unroll
            for (int i = 0; i < 4; i++){
                int idx = i * 256 + tid;         // 0..1023
                int n   = idx >> 4;              // 0..63
                int kq4 = idx & 15;
                float4 v = *(const float4*)(wproj + (n0 + n) * 128 + k0 + kq4 * 4);
                int base = (((n >> 3) * 8 + (kq4 >> 1)) * 32 + (n & 7) * 4) * 2 + (kq4 & 1);
                sW[base + 0*2] = to_tf32(v.x);
                sW[base + 1*2] = to_tf32(v.y);
                sW[base + 2*2] = to_tf32(v.z);
                sW[base + 3*2] = to_tf32(v.w);
            }
        }
        __syncthreads();

#pragma unroll
        for (int k8 = 0; k8 < 8; k8++){
            float4 af[2];
#pragma unroll
            for (int mt = 0; mt < 2; mt++)
                af[mt] = *(const float4*)&sA[(((warpM * 2 + mt) * 8 + k8) * 32 + lane) * 4];
            float2 bf[4];
#pragma unroll
            for (int nt = 0; nt < 4; nt++)
                bf[nt] = *(const float2*)&sW[(((warpN * 4 + nt) * 8 + k8) * 32 + lane) * 2];
#pragma unroll
            for (int mt = 0; mt < 2; mt++)
#pragma unroll
                for (int nt = 0; nt < 4; nt++){
                    asm volatile(
                        "mma.sync.aligned.m16n8k8.row.col.f32.tf32.tf32.f32 "
                        "{%0,%1,%2,%3},{%4,%5,%6,%7},{%8,%9},{%0,%1,%2,%3};"
                        : "+f"(acc[mt][nt][0]), "+f"(acc[mt][nt][1]),
                          "+f"(acc[mt][nt][2]), "+f"(acc[mt][nt][3])
                        : "r"(__float_as_uint(af[mt].x)), "r"(__float_as_uint(af[mt].y)),
                          "r"(__float_as_uint(af[mt].z)), "r"(__float_as_uint(af[mt].w)),
                          "r"(__float_as_uint(bf[nt].x)), "r"(__float_as_uint(bf[nt].y)));
                }
        }
        __syncthreads();
    }

    const bool is_x = (n0 < 256);
    float* sE = smem_all;                // reuse; up to 131 rows x stride 72

    if (is_x){
        // ---- stage RAW tile at rows 3..130 ----
#pragma unroll
        for (int mt = 0; mt < 2; mt++)
#pragma unroll
            for (int nt = 0; nt < 4; nt++)
#pragma unroll
                for (int rh = 0; rh < 2; rh++){
                    int ml = warpM * 32 + mt * 16 + (lane >> 2) + rh * 8;
                    int nl = warpN * 32 + nt * 8 + (lane & 3) * 2;
                    *(float2*)&sE[(ml + 3) * 72 + nl] =
                        make_float2(acc[mt][nt][rh * 2 + 0], acc[mt][nt][rh * 2 + 1]);
                }
        // ---- halo rows 0..2: xcraw(m0-3..m0-1, n0..n0+63) via SIMT dot products ----
        if (tid < 192){
            int r  = tid >> 6;          // 0..2
            int ch = tid & 63;
            float s = 0.0f;
            if (l0 != 0){
                const float4* er = (const float4*)(emb + ids[m0 - 3 + r] * 128);
                const float4* wr = (const float4*)(wproj + (n0 + ch) * 128);
#pragma unroll 8
                for (int kk = 0; kk < 32; kk++){
                    float4 e4 = er[kk], w4 = wr[kk];
                    s = fmaf(e4.x, w4.x, s); s = fmaf(e4.y, w4.y, s);
                    s = fmaf(e4.z, w4.z, s); s = fmaf(e4.w, w4.w, s);
                }
            }
            sE[r * 72 + ch] = s;
        }
        __syncthreads();

        // ---- conv + bias + SiLU + store (each thread owns 4 fixed channels) ----
        const int q  = tid & 15;                // channel quad (invariant over i)
        const int dch = n0 + q * 4;
        float cw[4][4];
#pragma unroll
        for (int cqi = 0; cqi < 4; cqi++){
            float4 wq = __ldg((const float4*)(conv_w + (dch + cqi) * 4));
            cw[cqi][0] = wq.x; cw[cqi][1] = wq.y; cw[cqi][2] = wq.z; cw[cqi][3] = wq.w;
        }
        float4 bb = __ldg((const float4*)(conv_b + dch));
#pragma unroll
        for (int i = 0; i < 8; i++){
            int row = i * 16 + (tid >> 4);      // 0..127
            float4 x0 = *(const float4*)&sE[(row + 0) * 72 + q * 4];  // l-3
            float4 x1 = *(const float4*)&sE[(row + 1) * 72 + q * 4];  // l-2
            float4 x2 = *(const float4*)&sE[(row + 2) * 72 + q * 4];  // l-1
            float4 x3 = *(const float4*)&sE[(row + 3) * 72 + q * 4];  // l
            float a0 = bb.x, a1 = bb.y, a2 = bb.z, a3 = bb.w;
            a0 = fmaf(cw[0][0], x0.x, a0); a1 = fmaf(cw[1][0], x0.y, a1);
            a2 = fmaf(cw[2][0], x0.z, a2); a3 = fmaf(cw[3][0], x0.w, a3);
            a0 = fmaf(cw[0][1], x1.x, a0); a1 = fmaf(cw[1][1], x1.y, a1);
            a2 = fmaf(cw[2][1], x1.z, a2); a3 = fmaf(cw[3][1], x1.w, a3);
            a0 = fmaf(cw[0][2], x2.x, a0); a1 = fmaf(cw[1][2], x2.y, a1);
            a2 = fmaf(cw[2][2], x2.z, a2); a3 = fmaf(cw[3][2], x2.w, a3);
            a0 = fmaf(cw[0][3], x3.x, a0); a1 = fmaf(cw[1][3], x3.y, a1);
            a2 = fmaf(cw[2][3], x3.z, a2); a3 = fmaf(cw[3][3], x3.w, a3);
            float4 o;
            o.x = silu_f(a0); o.y = silu_f(a1); o.z = silu_f(a2); o.w = silu_f(a3);
            *(float4*)(g_xc + (m0 + row) * 256 + dch) = o;
        }
    } else {
        // ---- z half: SiLU, stage, coalesced store to g_gate ----
#pragma unroll
        for (int mt = 0; mt < 2; mt++)
#pragma unroll
            for (int nt = 0; nt < 4; nt++)
#pragma unroll
                for (int rh = 0; rh < 2; rh++){
                    int ml = warpM * 32 + mt * 16 + (lane >> 2) + rh * 8;
                    int nl = warpN * 32 + nt * 8 + (lane & 3) * 2;
                    *(float2*)&sE[ml * 72 + nl] =
                        make_float2(silu_f(acc[mt][nt][rh * 2 + 0]),
                                    silu_f(acc[mt][nt][rh * 2 + 1]));
                }
        __syncthreads();
        const int ncol0 = n0 - 256;
#pragma unroll
        for (int i = 0; i < 8; i++){
            int idx = i * 256 + tid;         // 0..2047
            int row = idx >> 4;
            int q   = idx & 15;
            float4 v = *(const float4*)&sE[row * 72 + q * 4];
            *(float4*)(g_gate + (m0 + row) * 256 + ncol0 + q * 4) = v;
        }
    }
}

// ---------------- K3: x_proj (40x256) + dt_proj (256x8) + softplus; emit {delta,xc}/B/C ----------------
__global__ void __launch_bounds__(256) k3_xproj(const float* __restrict__ xpw,
                                                const float* __restrict__ dtw,
                                                const float* __restrict__ dtb)
{
    __shared__ __align__(16) float sw[40 * 256];
    __shared__ float sdbc[8][4][40];
    const int tid  = threadIdx.x;
    const int lane = tid & 31;
    const int wp   = tid >> 5;
    const int bl0  = (blockIdx.x * 8 + wp) * 4;

#pragma unroll
    for (int i = 0; i < 10; i++)
        ((float4*)sw)[i * 256 + tid] = ((const float4*)xpw)[i * 256 + tid];
    __syncthreads();

    float xcl[4][8];
#pragma unroll
    for (int p = 0; p < 4; p++)
#pragma unroll
        for (int k = 0; k < 8; k++)
            xcl[p][k] = g_xc[(bl0 + p) * 256 + k * 32 + lane];

#pragma unroll 8
    for (int j = 0; j < 40; j++){
        float wl[8];
#pragma unroll
        for (int k = 0; k < 8; k++) wl[k] = sw[j * 256 + k * 32 + lane];
        float s0 = 0.f, s1 = 0.f, s2 = 0.f, s3 = 0.f;
#pragma unroll
        for (int k = 0; k < 8; k++){
            s0 = fmaf(wl[k], xcl[0][k], s0);
            s1 = fmaf(wl[k], xcl[1][k], s1);
            s2 = fmaf(wl[k], xcl[2][k], s2);
            s3 = fmaf(wl[k], xcl[3][k], s3);
        }
#pragma unroll
        for (int off = 16; off; off >>= 1){
            s0 += __shfl_xor_sync(0xffffffffu, s0, off);
            s1 += __shfl_xor_sync(0xffffffffu, s1, off);
            s2 += __shfl_xor_sync(0xffffffffu, s2, off);
            s3 += __shfl_xor_sync(0xffffffffu, s3, off);
        }
        if (lane == 0){
            sdbc[wp][0][j] = s0; sdbc[wp][1][j] = s1;
            sdbc[wp][2][j] = s2; sdbc[wp][3][j] = s3;
        }
    }
    __syncwarp();

    if (lane < 16){
#pragma unroll
        for (int p = 0; p < 4; p++){
            g_Bm[(bl0 + p) * 16 + lane] = sdbc[wp][p][8  + lane];
            g_Cm[(bl0 + p) * 16 + lane] = sdbc[wp][p][24 + lane];
        }
    }

#pragma unroll
    for (int k = 0; k < 8; k++){
        int d = k * 32 + lane;
        float4 w0 = __ldg((const float4*)(dtw + d * 8));
        float4 w1 = __ldg((const float4*)(dtw + d * 8 + 4));
        float bias = __ldg(dtb + d);
#pragma unroll
        for (int p = 0; p < 4; p++){
            const float* dv = sdbc[wp][p];
            float t = bias;
            t = fmaf(w0.x, dv[0], t); t = fmaf(w0.y, dv[1], t);
            t = fmaf(w0.z, dv[2], t); t = fmaf(w0.w, dv[3], t);
            t = fmaf(w1.x, dv[4], t); t = fmaf(w1.y, dv[5], t);
            t = fmaf(w1.z, dv[6], t); t = fmaf(w1.w, dv[7], t);
            g_dxc[(bl0 + p) * 256 + d] = make_float2(softplus_f(t), xcl[p][k]);
        }
    }
}

// ---------------- K4: chunked selective scan, pass A ----------------
// Warp-half sh: tid<128 -> states 0..7, tid>=128 -> states 8..15 of channel d=tid&127.
// In-kernel exp (e1 per 4-step batch) and D-term; merged gC = gv*C gating.
// Chunk state written channel-fastest (coalesced float4 quads).
__global__ void __launch_bounds__(256, 3) k4_scan(const float* __restrict__ A_log,
                                                  const float* __restrict__ Dvec)
{
    __shared__ __align__(16) float sB[CLEN * 16];
    __shared__ __align__(16) float sC[CLEN * 16];
    __shared__ float sacc[128];

    const int b   = blockIdx.x >> 6;         // 32 chunks * 2 channel-halves
    const int c   = (blockIdx.x >> 1) & 31;
    const int hb  = blockIdx.x & 1;          // channel-half block
    const int tid = threadIdx.x;
    const int sh  = tid >> 7;                // state half (warp-uniform)
    const int dl  = tid & 127;
    const int d   = hb * 128 + dl;
    const int n0  = sh * 8;

    const float An0 = -__expf(__ldg(A_log + d * 16));
    bool pw_ok = true;
#pragma unroll
    for (int j = 0; j < 8; j++){
        float Ann = -__expf(__ldg(A_log + d * 16 + n0 + j));
        pw_ok = pw_ok && (fabsf(Ann / An0 - (float)(n0 + j + 1)) < 1e-3f);
    }
    const float Dd_eff = sh ? 0.0f : __ldg(Dvec + d);   // only half 0 adds the D term

    const int l0 = b * Lsz + c * CLEN;
    {
        const float4* gB = (const float4*)(g_Bm + l0 * 16);
        const float4* gC4 = (const float4*)(g_Cm + l0 * 16);
        ((float4*)sB)[tid] = gB[tid];
        ((float4*)sC)[tid] = gC4[tid];
    }
    __syncthreads();

    float h[8], P[8], S[8];
#pragma unroll
    for (int j = 0; j < 8; j++){ h[j] = 0.0f; P[j] = 1.0f; S[j] = 0.0f; }
    float accl = 0.0f;

    int base = l0 * 256 + d;

    if (pw_ok){
        float2 pdx[4]; float pg[4];
#pragma unroll
        for (int q = 0; q < 4; q++){
            pdx[q] = g_dxc[base + q * 256];
            pg[q]  = __ldg(g_gate + base + q * 256);
        }
#pragma unroll 1
        for (int t = 0; t < CLEN; t += 4){
            float2 cdx[4]; float cg[4];
#pragma unroll
            for (int q = 0; q < 4; q++){ cdx[q] = pdx[q]; cg[q] = pg[q]; }
            int nb = base + 4 * 256;
            if (t + 4 < CLEN){
#pragma unroll
                for (int q = 0; q < 4; q++){
                    pdx[q] = g_dxc[nb + q * 256];
                    pg[q]  = __ldg(g_gate + nb + q * 256);
                }
            }
            float e1v[4];
#pragma unroll
            for (int q = 0; q < 4; q++) e1v[q] = __expf(cdx[q].x * An0);

#pragma unroll
            for (int q = 0; q < 4; q++){
                float gv  = cg[q];
                float xcv = cdx[q].y;
                float dxv = cdx[q].x * xcv;

                // powers e1^1..e1^8; upper half shifts by e1^8 (warp-uniform)
                float qp[8];
                qp[0] = e1v[q];
#pragma unroll
                for (int i = 1; i < 8; i++) qp[i] = qp[(i - 1) >> 1] * qp[i >> 1];
                if (sh){
                    float e8 = qp[7];
#pragma unroll
                    for (int j = 0; j < 8; j++) qp[j] *= e8;
                }

                float4 bb0 = ((const float4*)sB)[(t + q) * 4 + sh * 2 + 0];
                float4 bb1 = ((const float4*)sB)[(t + q) * 4 + sh * 2 + 1];
                float4 cc0 = ((const float4*)sC)[(t + q) * 4 + sh * 2 + 0];
                float4 cc1 = ((const float4*)sC)[(t + q) * 4 + sh * 2 + 1];
                float Bv[8] = {bb0.x, bb0.y, bb0.z, bb0.w, bb1.x, bb1.y, bb1.z, bb1.w};
                float gC[8] = {gv*cc0.x, gv*cc0.y, gv*cc0.z, gv*cc0.w,
                               gv*cc1.x, gv*cc1.y, gv*cc1.z, gv*cc1.w};

#pragma unroll
                for (int j = 0; j < 8; j++){
                    P[j] *= qp[j];
                    h[j] = fmaf(qp[j], h[j], dxv * Bv[j]);
                    accl = fmaf(h[j], gC[j], accl);
                    S[j] = fmaf(P[j], gC[j], S[j]);
                }
                accl = fmaf(gv * xcv, Dd_eff, accl);
            }
            base = nb;
        }
    } else {
        // cold generic path (correctness only)
#pragma unroll 1
        for (int t = 0; t < CLEN; t++){
            float2 dxc  = g_dxc[base];
            float delta = dxc.x;
            float xcv   = dxc.y;
            float gv    = g_gate[base];
            float dxv   = delta * xcv;
#pragma unroll 4
            for (int j = 0; j < 8; j++){
                float An = -__expf(__ldg(A_log + d * 16 + n0 + j));
                float dA = __expf(delta * An);
                float Bn = sB[t * 16 + n0 + j];
                float Cn = sC[t * 16 + n0 + j] * gv;
                P[j] *= dA;
                h[j] = fmaf(dA, h[j], dxv * Bn);
                accl = fmaf(h[j], Cn, accl);
                S[j] = fmaf(P[j], Cn, S[j]);
            }
            accl = fmaf(gv * xcv, Dd_eff, accl);
            base += 256;
        }
    }

    // cross-half combine (one smem word per channel)
    if (sh) sacc[dl] = accl;
    __syncthreads();

    const int cb = b * NCH + c;
    if (!sh) g_accl[cb * DI + d] = accl + sacc[dl];
    // coalesced channel-fastest quad stores (lanes = consecutive d)
#pragma unroll
    for (int qq = 0; qq < 2; qq++){
        int q = sh * 2 + qq;
        g_P4[(cb * 4 + q) * DI + d] = make_float4(P[qq*4+0], P[qq*4+1], P[qq*4+2], P[qq*4+3]);
        g_h4[(cb * 4 + q) * DI + d] = make_float4(h[qq*4+0], h[qq*4+1], h[qq*4+2], h[qq*4+3]);
        g_S4[(cb * 4 + q) * DI + d] = make_float4(S[qq*4+0], S[qq*4+1], S[qq*4+2], S[qq*4+3]);
    }
}

// ---------------- K5: chunk combine + out_proj + mean + classifier (merged tail) ----------------
// One block per batch b (256 threads, one per channel d). All loads coalesced.
__global__ void __launch_bounds__(256) k5_tail(const float* __restrict__ opw,
                                               const float* __restrict__ clw,
                                               const float* __restrict__ clb,
                                               float* __restrict__ out)
{
    __shared__ float sacc[256];
    __shared__ float mvec[128];
    const int b   = blockIdx.x;
    const int tid = threadIdx.x;     // channel d

    float h[16];
#pragma unroll
    for (int n = 0; n < 16; n++) h[n] = 0.0f;
    float acc = 0.0f;
#pragma unroll 2
    for (int c = 0; c < NCH; c++){
        int cb = b * NCH + c;
        acc += g_accl[cb * DI + tid];
        float4 sv[4], pv[4], hv[4];
#pragma unroll
        for (int q = 0; q < 4; q++){
            sv[q] = g_S4[(cb * 4 + q) * DI + tid];
            pv[q] = g_P4[(cb * 4 + q) * DI + tid];
            hv[q] = g_h4[(cb * 4 + q) * DI + tid];
        }
#pragma unroll
        for (int q = 0; q < 4; q++){
            acc = fmaf(h[q*4+0], sv[q].x, acc);
            acc = fmaf(h[q*4+1], sv[q].y, acc);
            acc = fmaf(h[q*4+2], sv[q].z, acc);
            acc = fmaf(h[q*4+3], sv[q].w, acc);
            h[q*4+0] = fmaf(pv[q].x, h[q*4+0], hv[q].x);
            h[q*4+1] = fmaf(pv[q].y, h[q*4+1], hv[q].y);
            h[q*4+2] = fmaf(pv[q].z, h[q*4+2], hv[q].z);
            h[q*4+3] = fmaf(pv[q].w, h[q*4+3], hv[q].w);
        }
    }
    sacc[tid] = acc;
    __syncthreads();

    if (tid < 128){
        float s = 0.0f;
#pragma unroll 8
        for (int e = 0; e < 256; e++) s = fmaf(sacc[e], __ldg(opw + tid * 256 + e), s);
        mvec[tid] = s * (1.0f / 2048.0f);
    }
    __syncthreads();
    if (tid < 2){
        float t = __ldg(clb + tid);
#pragma unroll 8
        for (int e = 0; e < 128; e++) t = fmaf(mvec[e], __ldg(clw + tid * 128 + e), t);
        out[b * 2 + tid] = t;
    }
}

// ---------------- launch ----------------
extern "C" void kernel_launch(void* const* d_in, const int* in_sizes, int n_in,
                              void* d_out, int out_size)
{
    const int*   ids  = (const int*)  d_in[0];
    const float* emb  = (const float*)d_in[1];
    const float* ipw  = (const float*)d_in[2];
    const float* cw   = (const float*)d_in[3];
    const float* cb   = (const float*)d_in[4];
    const float* xpw  = (const float*)d_in[5];
    const float* dtw  = (const float*)d_in[6];
    const float* dtb  = (const float*)d_in[7];
    const float* alog = (const float*)d_in[8];
    const float* dvec = (const float*)d_in[9];
    const float* opw  = (const float*)d_in[10];
    const float* clw  = (const float*)d_in[11];
    const float* clb  = (const float*)d_in[12];
    float* out = (float*)d_out;

    dim3 g1(BLn / 128, 8);   // 256 m-tiles x 8 n-tiles of 64
    k1_inproj<<<g1, 256>>>(ids, emb, ipw, cw, cb);
    k3_xproj<<<BLn / 32, 256>>>(xpw, dtw, dtb);
    k4_scan<<<Bsz * NCH * 2, 256>>>(alog, dvec);
    k5_tail<<<Bsz, 256>>>(opw, clw, clb, out);
}

// round 12
// speedup vs baseline: 1.1729x; 1.0811x over previous
#include <cuda_runtime.h>
#include <math.h>
#include <stdint.h>

// Problem constants
#define Bsz 16
#define Lsz 2048
#define BLn (Bsz*Lsz)          // 32768 (b,l) positions
#define DI 256                 // d_inner
#define DS 16                  // d_state
#define NCH 32                 // scan chunks
#define CLEN (Lsz/NCH)         // 64 steps per chunk
#define NSEG 8                 // segments per batch (4 chunks each)

// ---------------- scratch (static device globals; no allocation) ----------------
static __device__ float  g_gate [BLn*DI];   // silu(z)
static __device__ float  g_xc   [BLn*DI];   // silu(conv(x))
static __device__ float2 g_dxc  [BLn*DI];   // packed {delta, xc} from K3
static __device__ float  g_Bm   [BLn*DS];
static __device__ float  g_Cm   [BLn*DS];
// chunk state, channel-fastest float4 quads: [((b*NCH+c)*4+q)*DI + d]
static __device__ float4 g_P4 [Bsz*NCH*4*DI];
static __device__ float4 g_h4 [Bsz*NCH*4*DI];
static __device__ float4 g_S4 [Bsz*NCH*4*DI];
static __device__ float  g_accl[Bsz*NCH*DI];     // [(b*NCH+c)*DI + d]
// segment state (4 chunks combined): [((b*NSEG+s)*4+q)*DI + d]
static __device__ float4 g_Ps4[Bsz*NSEG*4*DI];
static __device__ float4 g_hs4[Bsz*NSEG*4*DI];
static __device__ float4 g_Ss4[Bsz*NSEG*4*DI];
static __device__ float  g_accs[Bsz*NSEG*DI];

__device__ __forceinline__ float silu_f(float x){ return x / (1.0f + __expf(-x)); }
__device__ __forceinline__ float softplus_f(float x){ return (x > 20.0f) ? x : log1pf(__expf(x)); }
__device__ __forceinline__ float to_tf32(float x){
    uint32_t u; asm("cvt.rna.tf32.f32 %0, %1;" : "=r"(u) : "f"(x));
    return __uint_as_float(u);
}

// ---------------- K1: embedding gather + in_proj GEMM (tf32 mma) + FUSED depthwise conv ----------------
__global__ void __launch_bounds__(256) k1_inproj(const int* __restrict__ ids,
                                                 const float* __restrict__ emb,
                                                 const float* __restrict__ wproj,
                                                 const float* __restrict__ conv_w,
                                                 const float* __restrict__ conv_b)
{
    __shared__ __align__(16) float smem_all[12288];   // 48 KB
    float* sA = smem_all;           // 8*8*32*4 = 8192 floats (32 KB)
    float* sW = smem_all + 8192;    // 8*8*32*2 = 4096 floats (16 KB)

    const int tid   = threadIdx.x;
    const int lane  = tid & 31;
    const int w     = tid >> 5;
    const int warpM = w >> 1;       // 0..3  (32 rows each)
    const int warpN = w & 1;        // 0..1  (32 cols each)
    const int m0 = blockIdx.x * 128;
    const int n0 = blockIdx.y * 64;
    const int l0 = m0 & (Lsz - 1);  // 0 or >=128 (tiles never straddle batches)

    int rid[8];
#pragma unroll
    for (int i = 0; i < 8; i++) rid[i] = ids[m0 + i * 16 + (tid >> 4)];

    float acc[2][4][4];
#pragma unroll
    for (int mt = 0; mt < 2; mt++)
#pragma unroll
        for (int nt = 0; nt < 4; nt++)
#pragma unroll
            for (int r = 0; r < 4; r++) acc[mt][nt][r] = 0.0f;

#pragma unroll 1
    for (int pass = 0; pass < 2; pass++){
        const int k0 = pass * 64;

        // ---- fill A: 128 rows x 64 k (tf32), fragment-permuted ----
        {
            const int kq4 = tid & 15;
#pragma unroll
            for (int i = 0; i < 8; i++){
                int row = i * 16 + (tid >> 4);
                float4 v = *(const float4*)(emb + rid[i] * 128 + k0 + kq4 * 4);
                int base = (((row >> 4) * 8 + (kq4 >> 1)) * 32 + (row & 7) * 4) * 4
                           + ((row >> 3) & 1) + 2 * (kq4 & 1);
                sA[base + 0*4] = to_tf32(v.x);
                sA[base + 1*4] = to_tf32(v.y);
                sA[base + 2*4] = to_tf32(v.z);
                sA[base + 3*4] = to_tf32(v.w);
            }
        }
        // ---- fill W: 64 rows x 64 k (tf32), fragment-permuted ----
        {
#pragma unroll
            for (int i = 0; i < 4; i++){
                int idx = i * 256 + tid;         // 0..1023
                int n   = idx >> 4;              // 0..63
                int kq4 = idx & 15;
                float4 v = *(const float4*)(wproj + (n0 + n) * 128 + k0 + kq4 * 4);
                int base = (((n >> 3) * 8 + (kq4 >> 1)) * 32 + (n & 7) * 4) * 2 + (kq4 & 1);
                sW[base + 0*2] = to_tf32(v.x);
                sW[base + 1*2] = to_tf32(v.y);
                sW[base + 2*2] = to_tf32(v.z);
                sW[base + 3*2] = to_tf32(v.w);
            }
        }
        __syncthreads();

#pragma unroll
        for (int k8 = 0; k8 < 8; k8++){
            float4 af[2];
#pragma unroll
            for (int mt = 0; mt < 2; mt++)
                af[mt] = *(const float4*)&sA[(((warpM * 2 + mt) * 8 + k8) * 32 + lane) * 4];
            float2 bf[4];
#pragma unroll
            for (int nt = 0; nt < 4; nt++)
                bf[nt] = *(const float2*)&sW[(((warpN * 4 + nt) * 8 + k8) * 32 + lane) * 2];
#pragma unroll
            for (int mt = 0; mt < 2; mt++)
#pragma unroll
                for (int nt = 0; nt < 4; nt++){
                    asm volatile(
                        "mma.sync.aligned.m16n8k8.row.col.f32.tf32.tf32.f32 "
                        "{%0,%1,%2,%3},{%4,%5,%6,%7},{%8,%9},{%0,%1,%2,%3};"
                        : "+f"(acc[mt][nt][0]), "+f"(acc[mt][nt][1]),
                          "+f"(acc[mt][nt][2]), "+f"(acc[mt][nt][3])
                        : "r"(__float_as_uint(af[mt].x)), "r"(__float_as_uint(af[mt].y)),
                          "r"(__float_as_uint(af[mt].z)), "r"(__float_as_uint(af[mt].w)),
                          "r"(__float_as_uint(bf[nt].x)), "r"(__float_as_uint(bf[nt].y)));
                }
        }
        __syncthreads();
    }

    const bool is_x = (n0 < 256);
    float* sE = smem_all;                // reuse; up to 131 rows x stride 72

    if (is_x){
        // ---- stage RAW tile at rows 3..130 ----
#pragma unroll
        for (int mt = 0; mt < 2; mt++)
#pragma unroll
            for (int nt = 0; nt < 4; nt++)
#pragma unroll
                for (int rh = 0; rh < 2; rh++){
                    int ml = warpM * 32 + mt * 16 + (lane >> 2) + rh * 8;
                    int nl = warpN * 32 + nt * 8 + (lane & 3) * 2;
                    *(float2*)&sE[(ml + 3) * 72 + nl] =
                        make_float2(acc[mt][nt][rh * 2 + 0], acc[mt][nt][rh * 2 + 1]);
                }
        // ---- halo rows 0..2 ----
        if (tid < 192){
            int r  = tid >> 6;          // 0..2
            int ch = tid & 63;
            float s = 0.0f;
            if (l0 != 0){
                const float4* er = (const float4*)(emb + ids[m0 - 3 + r] * 128);
                const float4* wr = (const float4*)(wproj + (n0 + ch) * 128);
#pragma unroll 8
                for (int kk = 0; kk < 32; kk++){
                    float4 e4 = er[kk], w4 = wr[kk];
                    s = fmaf(e4.x, w4.x, s); s = fmaf(e4.y, w4.y, s);
                    s = fmaf(e4.z, w4.z, s); s = fmaf(e4.w, w4.w, s);
                }
            }
            sE[r * 72 + ch] = s;
        }
        __syncthreads();

        // ---- conv + bias + SiLU + store ----
        const int q  = tid & 15;
        const int dch = n0 + q * 4;
        float cw[4][4];
#pragma unroll
        for (int cqi = 0; cqi < 4; cqi++){
            float4 wq = __ldg((const float4*)(conv_w + (dch + cqi) * 4));
            cw[cqi][0] = wq.x; cw[cqi][1] = wq.y; cw[cqi][2] = wq.z; cw[cqi][3] = wq.w;
        }
        float4 bb = __ldg((const float4*)(conv_b + dch));
#pragma unroll
        for (int i = 0; i < 8; i++){
            int row = i * 16 + (tid >> 4);
            float4 x0 = *(const float4*)&sE[(row + 0) * 72 + q * 4];
            float4 x1 = *(const float4*)&sE[(row + 1) * 72 + q * 4];
            float4 x2 = *(const float4*)&sE[(row + 2) * 72 + q * 4];
            float4 x3 = *(const float4*)&sE[(row + 3) * 72 + q * 4];
            float a0 = bb.x, a1 = bb.y, a2 = bb.z, a3 = bb.w;
            a0 = fmaf(cw[0][0], x0.x, a0); a1 = fmaf(cw[1][0], x0.y, a1);
            a2 = fmaf(cw[2][0], x0.z, a2); a3 = fmaf(cw[3][0], x0.w, a3);
            a0 = fmaf(cw[0][1], x1.x, a0); a1 = fmaf(cw[1][1], x1.y, a1);
            a2 = fmaf(cw[2][1], x1.z, a2); a3 = fmaf(cw[3][1], x1.w, a3);
            a0 = fmaf(cw[0][2], x2.x, a0); a1 = fmaf(cw[1][2], x2.y, a1);
            a2 = fmaf(cw[2][2], x2.z, a2); a3 = fmaf(cw[3][2], x2.w, a3);
            a0 = fmaf(cw[0][3], x3.x, a0); a1 = fmaf(cw[1][3], x3.y, a1);
            a2 = fmaf(cw[2][3], x3.z, a2); a3 = fmaf(cw[3][3], x3.w, a3);
            float4 o;
            o.x = silu_f(a0); o.y = silu_f(a1); o.z = silu_f(a2); o.w = silu_f(a3);
            *(float4*)(g_xc + (m0 + row) * 256 + dch) = o;
        }
    } else {
        // ---- z half: SiLU, stage, coalesced store ----
#pragma unroll
        for (int mt = 0; mt < 2; mt++)
#pragma unroll
            for (int nt = 0; nt < 4; nt++)
#pragma unroll
                for (int rh = 0; rh < 2; rh++){
                    int ml = warpM * 32 + mt * 16 + (lane >> 2) + rh * 8;
                    int nl = warpN * 32 + nt * 8 + (lane & 3) * 2;
                    *(float2*)&sE[ml * 72 + nl] =
                        make_float2(silu_f(acc[mt][nt][rh * 2 + 0]),
                                    silu_f(acc[mt][nt][rh * 2 + 1]));
                }
        __syncthreads();
        const int ncol0 = n0 - 256;
#pragma unroll
        for (int i = 0; i < 8; i++){
            int idx = i * 256 + tid;
            int row = idx >> 4;
            int q   = idx & 15;
            float4 v = *(const float4*)&sE[row * 72 + q * 4];
            *(float4*)(g_gate + (m0 + row) * 256 + ncol0 + q * 4) = v;
        }
    }
}

// ---------------- K3: x_proj (40x256) + dt_proj (256x8) + softplus; emit {delta,xc}/B/C ----------------
__global__ void __launch_bounds__(256) k3_xproj(const float* __restrict__ xpw,
                                                const float* __restrict__ dtw,
                                                const float* __restrict__ dtb)
{
    __shared__ __align__(16) float sw[40 * 256];
    __shared__ float sdbc[8][4][40];
    const int tid  = threadIdx.x;
    const int lane = tid & 31;
    const int wp   = tid >> 5;
    const int bl0  = (blockIdx.x * 8 + wp) * 4;

#pragma unroll
    for (int i = 0; i < 10; i++)
        ((float4*)sw)[i * 256 + tid] = ((const float4*)xpw)[i * 256 + tid];
    __syncthreads();

    float xcl[4][8];
#pragma unroll
    for (int p = 0; p < 4; p++)
#pragma unroll
        for (int k = 0; k < 8; k++)
            xcl[p][k] = g_xc[(bl0 + p) * 256 + k * 32 + lane];

#pragma unroll 8
    for (int j = 0; j < 40; j++){
        float wl[8];
#pragma unroll
        for (int k = 0; k < 8; k++) wl[k] = sw[j * 256 + k * 32 + lane];
        float s0 = 0.f, s1 = 0.f, s2 = 0.f, s3 = 0.f;
#pragma unroll
        for (int k = 0; k < 8; k++){
            s0 = fmaf(wl[k], xcl[0][k], s0);
            s1 = fmaf(wl[k], xcl[1][k], s1);
            s2 = fmaf(wl[k], xcl[2][k], s2);
            s3 = fmaf(wl[k], xcl[3][k], s3);
        }
#pragma unroll
        for (int off = 16; off; off >>= 1){
            s0 += __shfl_xor_sync(0xffffffffu, s0, off);
            s1 += __shfl_xor_sync(0xffffffffu, s1, off);
            s2 += __shfl_xor_sync(0xffffffffu, s2, off);
            s3 += __shfl_xor_sync(0xffffffffu, s3, off);
        }
        if (lane == 0){
            sdbc[wp][0][j] = s0; sdbc[wp][1][j] = s1;
            sdbc[wp][2][j] = s2; sdbc[wp][3][j] = s3;
        }
    }
    __syncwarp();

    if (lane < 16){
#pragma unroll
        for (int p = 0; p < 4; p++){
            g_Bm[(bl0 + p) * 16 + lane] = sdbc[wp][p][8  + lane];
            g_Cm[(bl0 + p) * 16 + lane] = sdbc[wp][p][24 + lane];
        }
    }

#pragma unroll
    for (int k = 0; k < 8; k++){
        int d = k * 32 + lane;
        float4 w0 = __ldg((const float4*)(dtw + d * 8));
        float4 w1 = __ldg((const float4*)(dtw + d * 8 + 4));
        float bias = __ldg(dtb + d);
#pragma unroll
        for (int p = 0; p < 4; p++){
            const float* dv = sdbc[wp][p];
            float t = bias;
            t = fmaf(w0.x, dv[0], t); t = fmaf(w0.y, dv[1], t);
            t = fmaf(w0.z, dv[2], t); t = fmaf(w0.w, dv[3], t);
            t = fmaf(w1.x, dv[4], t); t = fmaf(w1.y, dv[5], t);
            t = fmaf(w1.z, dv[6], t); t = fmaf(w1.w, dv[7], t);
            g_dxc[(bl0 + p) * 256 + d] = make_float2(softplus_f(t), xcl[p][k]);
        }
    }
}

// ---------------- K4: chunked selective scan, pass A ----------------
__global__ void __launch_bounds__(256, 3) k4_scan(const float* __restrict__ A_log,
                                                  const float* __restrict__ Dvec)
{
    __shared__ __align__(16) float sB[CLEN * 16];
    __shared__ __align__(16) float sC[CLEN * 16];
    __shared__ float sacc[128];

    const int b   = blockIdx.x >> 6;         // 32 chunks * 2 channel-halves
    const int c   = (blockIdx.x >> 1) & 31;
    const int hb  = blockIdx.x & 1;          // channel-half block
    const int tid = threadIdx.x;
    const int sh  = tid >> 7;                // state half (warp-uniform)
    const int dl  = tid & 127;
    const int d   = hb * 128 + dl;
    const int n0  = sh * 8;

    const float An0 = -__expf(__ldg(A_log + d * 16));
    bool pw_ok = true;
#pragma unroll
    for (int j = 0; j < 8; j++){
        float Ann = -__expf(__ldg(A_log + d * 16 + n0 + j));
        pw_ok = pw_ok && (fabsf(Ann / An0 - (float)(n0 + j + 1)) < 1e-3f);
    }
    const float Dd_eff = sh ? 0.0f : __ldg(Dvec + d);

    const int l0 = b * Lsz + c * CLEN;
    {
        const float4* gB = (const float4*)(g_Bm + l0 * 16);
        const float4* gC4 = (const float4*)(g_Cm + l0 * 16);
        ((float4*)sB)[tid] = gB[tid];
        ((float4*)sC)[tid] = gC4[tid];
    }
    __syncthreads();

    float h[8], P[8], S[8];
#pragma unroll
    for (int j = 0; j < 8; j++){ h[j] = 0.0f; P[j] = 1.0f; S[j] = 0.0f; }
    float accl = 0.0f;

    int base = l0 * 256 + d;

    if (pw_ok){
        float2 pdx[4]; float pg[4];
#pragma unroll
        for (int q = 0; q < 4; q++){
            pdx[q] = g_dxc[base + q * 256];
            pg[q]  = __ldg(g_gate + base + q * 256);
        }
#pragma unroll 1
        for (int t = 0; t < CLEN; t += 4){
            float2 cdx[4]; float cg[4];
#pragma unroll
            for (int q = 0; q < 4; q++){ cdx[q] = pdx[q]; cg[q] = pg[q]; }
            int nb = base + 4 * 256;
            if (t + 4 < CLEN){
#pragma unroll
                for (int q = 0; q < 4; q++){
                    pdx[q] = g_dxc[nb + q * 256];
                    pg[q]  = __ldg(g_gate + nb + q * 256);
                }
            }
            float e1v[4];
#pragma unroll
            for (int q = 0; q < 4; q++) e1v[q] = __expf(cdx[q].x * An0);

#pragma unroll
            for (int q = 0; q < 4; q++){
                float gv  = cg[q];
                float xcv = cdx[q].y;
                float dxv = cdx[q].x * xcv;

                float qp[8];
                qp[0] = e1v[q];
#pragma unroll
                for (int i = 1; i < 8; i++) qp[i] = qp[(i - 1) >> 1] * qp[i >> 1];
                if (sh){
                    float e8 = qp[7];
#pragma unroll
                    for (int j = 0; j < 8; j++) qp[j] *= e8;
                }

                float4 bb0 = ((const float4*)sB)[(t + q) * 4 + sh * 2 + 0];
                float4 bb1 = ((const float4*)sB)[(t + q) * 4 + sh * 2 + 1];
                float4 cc0 = ((const float4*)sC)[(t + q) * 4 + sh * 2 + 0];
                float4 cc1 = ((const float4*)sC)[(t + q) * 4 + sh * 2 + 1];
                float Bv[8] = {bb0.x, bb0.y, bb0.z, bb0.w, bb1.x, bb1.y, bb1.z, bb1.w};
                float gC[8] = {gv*cc0.x, gv*cc0.y, gv*cc0.z, gv*cc0.w,
                               gv*cc1.x, gv*cc1.y, gv*cc1.z, gv*cc1.w};

#pragma unroll
                for (int j = 0; j < 8; j++){
                    P[j] *= qp[j];
                    h[j] = fmaf(qp[j], h[j], dxv * Bv[j]);
                    accl = fmaf(h[j], gC[j], accl);
                    S[j] = fmaf(P[j], gC[j], S[j]);
                }
                accl = fmaf(gv * xcv, Dd_eff, accl);
            }
            base = nb;
        }
    } else {
        // cold generic path (correctness only)
#pragma unroll 1
        for (int t = 0; t < CLEN; t++){
            float2 dxc  = g_dxc[base];
            float delta = dxc.x;
            float xcv   = dxc.y;
            float gv    = g_gate[base];
            float dxv   = delta * xcv;
#pragma unroll 4
            for (int j = 0; j < 8; j++){
                float An = -__expf(__ldg(A_log + d * 16 + n0 + j));
                float dA = __expf(delta * An);
                float Bn = sB[t * 16 + n0 + j];
                float Cn = sC[t * 16 + n0 + j] * gv;
                P[j] *= dA;
                h[j] = fmaf(dA, h[j], dxv * Bn);
                accl = fmaf(h[j], Cn, accl);
                S[j] = fmaf(P[j], Cn, S[j]);
            }
            accl = fmaf(gv * xcv, Dd_eff, accl);
            base += 256;
        }
    }

    if (sh) sacc[dl] = accl;
    __syncthreads();

    const int cb = b * NCH + c;
    if (!sh) g_accl[cb * DI + d] = accl + sacc[dl];
#pragma unroll
    for (int qq = 0; qq < 2; qq++){
        int q = sh * 2 + qq;
        g_P4[(cb * 4 + q) * DI + d] = make_float4(P[qq*4+0], P[qq*4+1], P[qq*4+2], P[qq*4+3]);
        g_h4[(cb * 4 + q) * DI + d] = make_float4(h[qq*4+0], h[qq*4+1], h[qq*4+2], h[qq*4+3]);
        g_S4[(cb * 4 + q) * DI + d] = make_float4(S[qq*4+0], S[qq*4+1], S[qq*4+2], S[qq*4+3]);
    }
}

// ---------------- K5a: combine 4 chunks -> 1 segment (associative composition) ----------------
// grid = Bsz * NSEG (128 blocks), 256 threads (one per channel d).
// Segment state (Pg, hg, Sg, a) composed left-to-right over its 4 chunks:
//   a  += a2 + sum_n hg[n]*S2[n];  Sg[n] += Pg[n]*S2[n];
//   hg[n] = P2[n]*hg[n] + hl2[n];  Pg[n] *= P2[n];
__global__ void __launch_bounds__(256) k5a_combine()
{
    const int b   = blockIdx.x >> 3;
    const int s   = blockIdx.x & (NSEG - 1);
    const int tid = threadIdx.x;     // channel d

    float Pg[16], hg[16], Sg[16];
#pragma unroll
    for (int n = 0; n < 16; n++){ Pg[n] = 1.0f; hg[n] = 0.0f; Sg[n] = 0.0f; }
    float a = 0.0f;

#pragma unroll
    for (int ci = 0; ci < 4; ci++){
        int cb = (b * NCH + s * 4 + ci);
        float a2 = g_accl[cb * DI + tid];
        float4 sv[4], pv[4], hv[4];
#pragma unroll
        for (int q = 0; q < 4; q++){
            sv[q] = g_S4[(cb * 4 + q) * DI + tid];
            pv[q] = g_P4[(cb * 4 + q) * DI + tid];
            hv[q] = g_h4[(cb * 4 + q) * DI + tid];
        }
        a += a2;
#pragma unroll
        for (int q = 0; q < 4; q++){
            a = fmaf(hg[q*4+0], sv[q].x, a);
            a = fmaf(hg[q*4+1], sv[q].y, a);
            a = fmaf(hg[q*4+2], sv[q].z, a);
            a = fmaf(hg[q*4+3], sv[q].w, a);
            Sg[q*4+0] = fmaf(Pg[q*4+0], sv[q].x, Sg[q*4+0]);
            Sg[q*4+1] = fmaf(Pg[q*4+1], sv[q].y, Sg[q*4+1]);
            Sg[q*4+2] = fmaf(Pg[q*4+2], sv[q].z, Sg[q*4+2]);
            Sg[q*4+3] = fmaf(Pg[q*4+3], sv[q].w, Sg[q*4+3]);
            hg[q*4+0] = fmaf(pv[q].x, hg[q*4+0], hv[q].x);
            hg[q*4+1] = fmaf(pv[q].y, hg[q*4+1], hv[q].y);
            hg[q*4+2] = fmaf(pv[q].z, hg[q*4+2], hv[q].z);
            hg[q*4+3] = fmaf(pv[q].w, hg[q*4+3], hv[q].w);
            Pg[q*4+0] *= pv[q].x; Pg[q*4+1] *= pv[q].y;
            Pg[q*4+2] *= pv[q].z; Pg[q*4+3] *= pv[q].w;
        }
    }

    const int sb = b * NSEG + s;
    g_accs[sb * DI + tid] = a;
#pragma unroll
    for (int q = 0; q < 4; q++){
        g_Ps4[(sb * 4 + q) * DI + tid] = make_float4(Pg[q*4+0], Pg[q*4+1], Pg[q*4+2], Pg[q*4+3]);
        g_hs4[(sb * 4 + q) * DI + tid] = make_float4(hg[q*4+0], hg[q*4+1], hg[q*4+2], hg[q*4+3]);
        g_Ss4[(sb * 4 + q) * DI + tid] = make_float4(Sg[q*4+0], Sg[q*4+1], Sg[q*4+2], Sg[q*4+3]);
    }
}

// ---------------- K5b: combine 8 segments + out_proj + mean + classifier ----------------
// One block per batch b (256 threads, one per channel d).
__global__ void __launch_bounds__(256) k5b_tail(const float* __restrict__ opw,
                                                const float* __restrict__ clw,
                                                const float* __restrict__ clb,
                                                float* __restrict__ out)
{
    __shared__ float sacc[256];
    __shared__ float mvec[128];
    const int b   = blockIdx.x;
    const int tid = threadIdx.x;     // channel d

    float h[16];
#pragma unroll
    for (int n = 0; n < 16; n++) h[n] = 0.0f;
    float acc = 0.0f;
#pragma unroll
    for (int s = 0; s < NSEG; s++){
        int sb = b * NSEG + s;
        acc += g_accs[sb * DI + tid];
        float4 sv[4], pv[4], hv[4];
#pragma unroll
        for (int q = 0; q < 4; q++){
            sv[q] = g_Ss4[(sb * 4 + q) * DI + tid];
            pv[q] = g_Ps4[(sb * 4 + q) * DI + tid];
            hv[q] = g_hs4[(sb * 4 + q) * DI + tid];
        }
#pragma unroll
        for (int q = 0; q < 4; q++){
            acc = fmaf(h[q*4+0], sv[q].x, acc);
            acc = fmaf(h[q*4+1], sv[q].y, acc);
            acc = fmaf(h[q*4+2], sv[q].z, acc);
            acc = fmaf(h[q*4+3], sv[q].w, acc);
            h[q*4+0] = fmaf(pv[q].x, h[q*4+0], hv[q].x);
            h[q*4+1] = fmaf(pv[q].y, h[q*4+1], hv[q].y);
            h[q*4+2] = fmaf(pv[q].z, h[q*4+2], hv[q].z);
            h[q*4+3] = fmaf(pv[q].w, h[q*4+3], hv[q].w);
        }
    }
    sacc[tid] = acc;
    __syncthreads();

    if (tid < 128){
        float s = 0.0f;
#pragma unroll 8
        for (int e = 0; e < 256; e++) s = fmaf(sacc[e], __ldg(opw + tid * 256 + e), s);
        mvec[tid] = s * (1.0f / 2048.0f);
    }
    __syncthreads();
    if (tid < 2){
        float t = __ldg(clb + tid);
#pragma unroll 8
        for (int e = 0; e < 128; e++) t = fmaf(mvec[e], __ldg(clw + tid * 128 + e), t);
        out[b * 2 + tid] = t;
    }
}

// ---------------- launch ----------------
extern "C" void kernel_launch(void* const* d_in, const int* in_sizes, int n_in,
                              void* d_out, int out_size)
{
    const int*   ids  = (const int*)  d_in[0];
    const float* emb  = (const float*)d_in[1];
    const float* ipw  = (const float*)d_in[2];
    const float* cw   = (const float*)d_in[3];
    const float* cb   = (const float*)d_in[4];
    const float* xpw  = (const float*)d_in[5];
    const float* dtw  = (const float*)d_in[6];
    const float* dtb  = (const float*)d_in[7];
    const float* alog = (const float*)d_in[8];
    const float* dvec = (const float*)d_in[9];
    const float* opw  = (const float*)d_in[10];
    const float* clw  = (const float*)d_in[11];
    const float* clb  = (const float*)d_in[12];
    float* out = (float*)d_out;

    dim3 g1(BLn / 128, 8);   // 256 m-tiles x 8 n-tiles of 64
    k1_inproj<<<g1, 256>>>(ids, emb, ipw, cw, cb);
    k3_xproj<<<BLn / 32, 256>>>(xpw, dtw, dtb);
    k4_scan<<<Bsz * NCH * 2, 256>>>(alog, dvec);
    k5a_combine<<<Bsz * NSEG, 256>>>();
    k5b_tail<<<Bsz, 256>>>(opw, clw, clb, out);
}

// round 13
// speedup vs baseline: 1.2266x; 1.0458x over previous
#include <cuda_runtime.h>
#include <math.h>
#include <stdint.h>

// Problem constants
#define Bsz 16
#define Lsz 2048
#define BLn (Bsz*Lsz)          // 32768 (b,l) positions
#define DI 256                 // d_inner
#define DS 16                  // d_state
#define NCH 32                 // scan chunks
#define CLEN (Lsz/NCH)         // 64 steps per chunk
#define NSEG 8                 // segments per batch (4 chunks each)

// ---------------- scratch (static device globals; no allocation) ----------------
static __device__ float  g_gate [BLn*DI];   // silu(z)
static __device__ float  g_xc   [BLn*DI];   // silu(conv(x))
static __device__ float2 g_dxc  [BLn*DI];   // packed {delta, xc} from K3
static __device__ float  g_Bm   [BLn*DS];
static __device__ float  g_Cm   [BLn*DS];
// chunk state, channel-fastest float4 quads: [((b*NCH+c)*4+q)*DI + d]
static __device__ float4 g_P4 [Bsz*NCH*4*DI];
static __device__ float4 g_h4 [Bsz*NCH*4*DI];
static __device__ float4 g_S4 [Bsz*NCH*4*DI];
static __device__ float  g_accl[Bsz*NCH*DI];     // [(b*NCH+c)*DI + d]
// segment state (4 chunks combined): [((b*NSEG+s)*4+q)*DI + d]
static __device__ float4 g_Ps4[Bsz*NSEG*4*DI];
static __device__ float4 g_hs4[Bsz*NSEG*4*DI];
static __device__ float4 g_Ss4[Bsz*NSEG*4*DI];
static __device__ float  g_accs[Bsz*NSEG*DI];

__device__ __forceinline__ float silu_f(float x){ return x / (1.0f + __expf(-x)); }
__device__ __forceinline__ float softplus_f(float x){ return (x > 20.0f) ? x : log1pf(__expf(x)); }
__device__ __forceinline__ float to_tf32(float x){
    uint32_t u; asm("cvt.rna.tf32.f32 %0, %1;" : "=r"(u) : "f"(x));
    return __uint_as_float(u);
}

// ---------------- K1: embedding gather + in_proj GEMM (tf32 mma) + FUSED depthwise conv ----------------
// BM=128 x BN=128 (two 64-wide n-subtiles share one A fill). ALL ns loops fully
// unrolled -> static acc indexing (the round-7 spill trap avoided).
__global__ void __launch_bounds__(256) k1_inproj(const int* __restrict__ ids,
                                                 const float* __restrict__ emb,
                                                 const float* __restrict__ wproj,
                                                 const float* __restrict__ conv_w,
                                                 const float* __restrict__ conv_b)
{
    __shared__ __align__(16) float smem_all[12288];   // 48 KB
    float* sA = smem_all;           // 8*8*32*4 = 8192 floats (32 KB)
    float* sW = smem_all + 8192;    // 8*8*32*2 = 4096 floats (16 KB)

    const int tid   = threadIdx.x;
    const int lane  = tid & 31;
    const int w     = tid >> 5;
    const int warpM = w >> 1;       // 0..3  (32 rows each)
    const int warpN = w & 1;        // 0..1  (32 cols each within 64-subtile)
    const int m0     = blockIdx.x * 128;
    const int n_base = blockIdx.y * 128;
    const int l0 = m0 & (Lsz - 1);  // 0 or >=128 (tiles never straddle batches)

    int rid[8];
#pragma unroll
    for (int i = 0; i < 8; i++) rid[i] = ids[m0 + i * 16 + (tid >> 4)];

    float acc[2][2][4][4];
#pragma unroll
    for (int ns = 0; ns < 2; ns++)
#pragma unroll
        for (int mt = 0; mt < 2; mt++)
#pragma unroll
            for (int nt = 0; nt < 4; nt++)
#pragma unroll
                for (int r = 0; r < 4; r++) acc[ns][mt][nt][r] = 0.0f;

#pragma unroll 1
    for (int pass = 0; pass < 2; pass++){
        const int k0 = pass * 64;

        // ---- fill A once per pass: 128 rows x 64 k (tf32), fragment-permuted ----
        {
            const int kq4 = tid & 15;
#pragma unroll
            for (int i = 0; i < 8; i++){
                int row = i * 16 + (tid >> 4);
                float4 v = *(const float4*)(emb + rid[i] * 128 + k0 + kq4 * 4);
                int base = (((row >> 4) * 8 + (kq4 >> 1)) * 32 + (row & 7) * 4) * 4
                           + ((row >> 3) & 1) + 2 * (kq4 & 1);
                sA[base + 0*4] = to_tf32(v.x);
                sA[base + 1*4] = to_tf32(v.y);
                sA[base + 2*4] = to_tf32(v.z);
                sA[base + 3*4] = to_tf32(v.w);
            }
        }

#pragma unroll
        for (int ns = 0; ns < 2; ns++){
            const int n0 = n_base + ns * 64;
            // ---- fill W: 64 rows x 64 k (tf32), fragment-permuted ----
#pragma unroll
            for (int i = 0; i < 4; i++){
                int idx = i * 256 + tid;         // 0..1023
                int n   = idx >> 4;              // 0..63
                int kq4 = idx & 15;
                float4 v = *(const float4*)(wproj + (n0 + n) * 128 + k0 + kq4 * 4);
                int base = (((n >> 3) * 8 + (kq4 >> 1)) * 32 + (n & 7) * 4) * 2 + (kq4 & 1);
                sW[base + 0*2] = to_tf32(v.x);
                sW[base + 1*2] = to_tf32(v.y);
                sW[base + 2*2] = to_tf32(v.z);
                sW[base + 3*2] = to_tf32(v.w);
            }
            __syncthreads();

#pragma unroll
            for (int k8 = 0; k8 < 8; k8++){
                float4 af[2];
#pragma unroll
                for (int mt = 0; mt < 2; mt++)
                    af[mt] = *(const float4*)&sA[(((warpM * 2 + mt) * 8 + k8) * 32 + lane) * 4];
                float2 bf[4];
#pragma unroll
                for (int nt = 0; nt < 4; nt++)
                    bf[nt] = *(const float2*)&sW[(((warpN * 4 + nt) * 8 + k8) * 32 + lane) * 2];
#pragma unroll
                for (int mt = 0; mt < 2; mt++)
#pragma unroll
                    for (int nt = 0; nt < 4; nt++){
                        asm volatile(
                            "mma.sync.aligned.m16n8k8.row.col.f32.tf32.tf32.f32 "
                            "{%0,%1,%2,%3},{%4,%5,%6,%7},{%8,%9},{%0,%1,%2,%3};"
                            : "+f"(acc[ns][mt][nt][0]), "+f"(acc[ns][mt][nt][1]),
                              "+f"(acc[ns][mt][nt][2]), "+f"(acc[ns][mt][nt][3])
                            : "r"(__float_as_uint(af[mt].x)), "r"(__float_as_uint(af[mt].y)),
                              "r"(__float_as_uint(af[mt].z)), "r"(__float_as_uint(af[mt].w)),
                              "r"(__float_as_uint(bf[nt].x)), "r"(__float_as_uint(bf[nt].y)));
                    }
            }
            __syncthreads();
        }
    }

    const bool is_x = (n_base < 256);
    float* sE = smem_all;                // reuse; up to 131 rows x stride 72

    if (is_x){
#pragma unroll
        for (int ns = 0; ns < 2; ns++){
            const int n0 = n_base + ns * 64;
            // ---- stage RAW subtile at rows 3..130 ----
#pragma unroll
            for (int mt = 0; mt < 2; mt++)
#pragma unroll
                for (int nt = 0; nt < 4; nt++)
#pragma unroll
                    for (int rh = 0; rh < 2; rh++){
                        int ml = warpM * 32 + mt * 16 + (lane >> 2) + rh * 8;
                        int nl = warpN * 32 + nt * 8 + (lane & 3) * 2;
                        *(float2*)&sE[(ml + 3) * 72 + nl] =
                            make_float2(acc[ns][mt][nt][rh * 2 + 0],
                                        acc[ns][mt][nt][rh * 2 + 1]);
                    }
            // ---- halo rows 0..2 for this subtile ----
            if (tid < 192){
                int r  = tid >> 6;          // 0..2
                int ch = tid & 63;
                float s = 0.0f;
                if (l0 != 0){
                    const float4* er = (const float4*)(emb + ids[m0 - 3 + r] * 128);
                    const float4* wr = (const float4*)(wproj + (n0 + ch) * 128);
#pragma unroll 8
                    for (int kk = 0; kk < 32; kk++){
                        float4 e4 = er[kk], w4 = wr[kk];
                        s = fmaf(e4.x, w4.x, s); s = fmaf(e4.y, w4.y, s);
                        s = fmaf(e4.z, w4.z, s); s = fmaf(e4.w, w4.w, s);
                    }
                }
                sE[r * 72 + ch] = s;
            }
            __syncthreads();

            // ---- conv + bias + SiLU + store ----
            const int q  = tid & 15;
            const int dch = n0 + q * 4;
            float cw[4][4];
#pragma unroll
            for (int cqi = 0; cqi < 4; cqi++){
                float4 wq = __ldg((const float4*)(conv_w + (dch + cqi) * 4));
                cw[cqi][0] = wq.x; cw[cqi][1] = wq.y; cw[cqi][2] = wq.z; cw[cqi][3] = wq.w;
            }
            float4 bb = __ldg((const float4*)(conv_b + dch));
#pragma unroll
            for (int i = 0; i < 8; i++){
                int row = i * 16 + (tid >> 4);
                float4 x0 = *(const float4*)&sE[(row + 0) * 72 + q * 4];
                float4 x1 = *(const float4*)&sE[(row + 1) * 72 + q * 4];
                float4 x2 = *(const float4*)&sE[(row + 2) * 72 + q * 4];
                float4 x3 = *(const float4*)&sE[(row + 3) * 72 + q * 4];
                float a0 = bb.x, a1 = bb.y, a2 = bb.z, a3 = bb.w;
                a0 = fmaf(cw[0][0], x0.x, a0); a1 = fmaf(cw[1][0], x0.y, a1);
                a2 = fmaf(cw[2][0], x0.z, a2); a3 = fmaf(cw[3][0], x0.w, a3);
                a0 = fmaf(cw[0][1], x1.x, a0); a1 = fmaf(cw[1][1], x1.y, a1);
                a2 = fmaf(cw[2][1], x1.z, a2); a3 = fmaf(cw[3][1], x1.w, a3);
                a0 = fmaf(cw[0][2], x2.x, a0); a1 = fmaf(cw[1][2], x2.y, a1);
                a2 = fmaf(cw[2][2], x2.z, a2); a3 = fmaf(cw[3][2], x2.w, a3);
                a0 = fmaf(cw[0][3], x3.x, a0); a1 = fmaf(cw[1][3], x3.y, a1);
                a2 = fmaf(cw[2][3], x3.z, a2); a3 = fmaf(cw[3][3], x3.w, a3);
                float4 o;
                o.x = silu_f(a0); o.y = silu_f(a1); o.z = silu_f(a2); o.w = silu_f(a3);
                *(float4*)(g_xc + (m0 + row) * 256 + dch) = o;
            }
            __syncthreads();
        }
    } else {
#pragma unroll
        for (int ns = 0; ns < 2; ns++){
            const int ncol0 = n_base - 256 + ns * 64;
#pragma unroll
            for (int mt = 0; mt < 2; mt++)
#pragma unroll
                for (int nt = 0; nt < 4; nt++)
#pragma unroll
                    for (int rh = 0; rh < 2; rh++){
                        int ml = warpM * 32 + mt * 16 + (lane >> 2) + rh * 8;
                        int nl = warpN * 32 + nt * 8 + (lane & 3) * 2;
                        *(float2*)&sE[ml * 72 + nl] =
                            make_float2(silu_f(acc[ns][mt][nt][rh * 2 + 0]),
                                        silu_f(acc[ns][mt][nt][rh * 2 + 1]));
                    }
            __syncthreads();
#pragma unroll
            for (int i = 0; i < 8; i++){
                int idx = i * 256 + tid;
                int row = idx >> 4;
                int q   = idx & 15;
                float4 v = *(const float4*)&sE[row * 72 + q * 4];
                *(float4*)(g_gate + (m0 + row) * 256 + ncol0 + q * 4) = v;
            }
            __syncthreads();
        }
    }
}

// ---------------- K3: x_proj (40x256) + dt_proj (256x8) + softplus; emit {delta,xc}/B/C ----------------
__global__ void __launch_bounds__(256) k3_xproj(const float* __restrict__ xpw,
                                                const float* __restrict__ dtw,
                                                const float* __restrict__ dtb)
{
    __shared__ __align__(16) float sw[40 * 256];
    __shared__ float sdbc[8][4][40];
    const int tid  = threadIdx.x;
    const int lane = tid & 31;
    const int wp   = tid >> 5;
    const int bl0  = (blockIdx.x * 8 + wp) * 4;

#pragma unroll
    for (int i = 0; i < 10; i++)
        ((float4*)sw)[i * 256 + tid] = ((const float4*)xpw)[i * 256 + tid];
    __syncthreads();

    float xcl[4][8];
#pragma unroll
    for (int p = 0; p < 4; p++)
#pragma unroll
        for (int k = 0; k < 8; k++)
            xcl[p][k] = g_xc[(bl0 + p) * 256 + k * 32 + lane];

#pragma unroll 8
    for (int j = 0; j < 40; j++){
        float wl[8];
#pragma unroll
        for (int k = 0; k < 8; k++) wl[k] = sw[j * 256 + k * 32 + lane];
        float s0 = 0.f, s1 = 0.f, s2 = 0.f, s3 = 0.f;
#pragma unroll
        for (int k = 0; k < 8; k++){
            s0 = fmaf(wl[k], xcl[0][k], s0);
            s1 = fmaf(wl[k], xcl[1][k], s1);
            s2 = fmaf(wl[k], xcl[2][k], s2);
            s3 = fmaf(wl[k], xcl[3][k], s3);
        }
#pragma unroll
        for (int off = 16; off; off >>= 1){
            s0 += __shfl_xor_sync(0xffffffffu, s0, off);
            s1 += __shfl_xor_sync(0xffffffffu, s1, off);
            s2 += __shfl_xor_sync(0xffffffffu, s2, off);
            s3 += __shfl_xor_sync(0xffffffffu, s3, off);
        }
        if (lane == 0){
            sdbc[wp][0][j] = s0; sdbc[wp][1][j] = s1;
            sdbc[wp][2][j] = s2; sdbc[wp][3][j] = s3;
        }
    }
    __syncwarp();

    if (lane < 16){
#pragma unroll
        for (int p = 0; p < 4; p++){
            g_Bm[(bl0 + p) * 16 + lane] = sdbc[wp][p][8  + lane];
            g_Cm[(bl0 + p) * 16 + lane] = sdbc[wp][p][24 + lane];
        }
    }

#pragma unroll
    for (int k = 0; k < 8; k++){
        int d = k * 32 + lane;
        float4 w0 = __ldg((const float4*)(dtw + d * 8));
        float4 w1 = __ldg((const float4*)(dtw + d * 8 + 4));
        float bias = __ldg(dtb + d);
#pragma unroll
        for (int p = 0; p < 4; p++){
            const float* dv = sdbc[wp][p];
            float t = bias;
            t = fmaf(w0.x, dv[0], t); t = fmaf(w0.y, dv[1], t);
            t = fmaf(w0.z, dv[2], t); t = fmaf(w0.w, dv[3], t);
            t = fmaf(w1.x, dv[4], t); t = fmaf(w1.y, dv[5], t);
            t = fmaf(w1.z, dv[6], t); t = fmaf(w1.w, dv[7], t);
            g_dxc[(bl0 + p) * 256 + d] = make_float2(softplus_f(t), xcl[p][k]);
        }
    }
}

// ---------------- K4: chunked selective scan, pass A ----------------
__global__ void __launch_bounds__(256, 3) k4_scan(const float* __restrict__ A_log,
                                                  const float* __restrict__ Dvec)
{
    __shared__ __align__(16) float sB[CLEN * 16];
    __shared__ __align__(16) float sC[CLEN * 16];
    __shared__ float sacc[128];

    const int b   = blockIdx.x >> 6;
    const int c   = (blockIdx.x >> 1) & 31;
    const int hb  = blockIdx.x & 1;
    const int tid = threadIdx.x;
    const int sh  = tid >> 7;
    const int dl  = tid & 127;
    const int d   = hb * 128 + dl;
    const int n0  = sh * 8;

    const float An0 = -__expf(__ldg(A_log + d * 16));
    bool pw_ok = true;
#pragma unroll
    for (int j = 0; j < 8; j++){
        float Ann = -__expf(__ldg(A_log + d * 16 + n0 + j));
        pw_ok = pw_ok && (fabsf(Ann / An0 - (float)(n0 + j + 1)) < 1e-3f);
    }
    const float Dd_eff = sh ? 0.0f : __ldg(Dvec + d);

    const int l0 = b * Lsz + c * CLEN;
    {
        const float4* gB = (const float4*)(g_Bm + l0 * 16);
        const float4* gC4 = (const float4*)(g_Cm + l0 * 16);
        ((float4*)sB)[tid] = gB[tid];
        ((float4*)sC)[tid] = gC4[tid];
    }
    __syncthreads();

    float h[8], P[8], S[8];
#pragma unroll
    for (int j = 0; j < 8; j++){ h[j] = 0.0f; P[j] = 1.0f; S[j] = 0.0f; }
    float accl = 0.0f;

    int base = l0 * 256 + d;

    if (pw_ok){
        float2 pdx[4]; float pg[4];
#pragma unroll
        for (int q = 0; q < 4; q++){
            pdx[q] = g_dxc[base + q * 256];
            pg[q]  = __ldg(g_gate + base + q * 256);
        }
#pragma unroll 1
        for (int t = 0; t < CLEN; t += 4){
            float2 cdx[4]; float cg[4];
#pragma unroll
            for (int q = 0; q < 4; q++){ cdx[q] = pdx[q]; cg[q] = pg[q]; }
            int nb = base + 4 * 256;
            if (t + 4 < CLEN){
#pragma unroll
                for (int q = 0; q < 4; q++){
                    pdx[q] = g_dxc[nb + q * 256];
                    pg[q]  = __ldg(g_gate + nb + q * 256);
                }
            }
            float e1v[4];
#pragma unroll
            for (int q = 0; q < 4; q++) e1v[q] = __expf(cdx[q].x * An0);

#pragma unroll
            for (int q = 0; q < 4; q++){
                float gv  = cg[q];
                float xcv = cdx[q].y;
                float dxv = cdx[q].x * xcv;

                float qp[8];
                qp[0] = e1v[q];
#pragma unroll
                for (int i = 1; i < 8; i++) qp[i] = qp[(i - 1) >> 1] * qp[i >> 1];
                if (sh){
                    float e8 = qp[7];
#pragma unroll
                    for (int j = 0; j < 8; j++) qp[j] *= e8;
                }

                float4 bb0 = ((const float4*)sB)[(t + q) * 4 + sh * 2 + 0];
                float4 bb1 = ((const float4*)sB)[(t + q) * 4 + sh * 2 + 1];
                float4 cc0 = ((const float4*)sC)[(t + q) * 4 + sh * 2 + 0];
                float4 cc1 = ((const float4*)sC)[(t + q) * 4 + sh * 2 + 1];
                float Bv[8] = {bb0.x, bb0.y, bb0.z, bb0.w, bb1.x, bb1.y, bb1.z, bb1.w};
                float gC[8] = {gv*cc0.x, gv*cc0.y, gv*cc0.z, gv*cc0.w,
                               gv*cc1.x, gv*cc1.y, gv*cc1.z, gv*cc1.w};

#pragma unroll
                for (int j = 0; j < 8; j++){
                    P[j] *= qp[j];
                    h[j] = fmaf(qp[j], h[j], dxv * Bv[j]);
                    accl = fmaf(h[j], gC[j], accl);
                    S[j] = fmaf(P[j], gC[j], S[j]);
                }
                accl = fmaf(gv * xcv, Dd_eff, accl);
            }
            base = nb;
        }
    } else {
#pragma unroll 1
        for (int t = 0; t < CLEN; t++){
            float2 dxc  = g_dxc[base];
            float delta = dxc.x;
            float xcv   = dxc.y;
            float gv    = g_gate[base];
            float dxv   = delta * xcv;
#pragma unroll 4
            for (int j = 0; j < 8; j++){
                float An = -__expf(__ldg(A_log + d * 16 + n0 + j));
                float dA = __expf(delta * An);
                float Bn = sB[t * 16 + n0 + j];
                float Cn = sC[t * 16 + n0 + j] * gv;
                P[j] *= dA;
                h[j] = fmaf(dA, h[j], dxv * Bn);
                accl = fmaf(h[j], Cn, accl);
                S[j] = fmaf(P[j], Cn, S[j]);
            }
            accl = fmaf(gv * xcv, Dd_eff, accl);
            base += 256;
        }
    }

    if (sh) sacc[dl] = accl;
    __syncthreads();

    const int cb = b * NCH + c;
    if (!sh) g_accl[cb * DI + d] = accl + sacc[dl];
#pragma unroll
    for (int qq = 0; qq < 2; qq++){
        int q = sh * 2 + qq;
        g_P4[(cb * 4 + q) * DI + d] = make_float4(P[qq*4+0], P[qq*4+1], P[qq*4+2], P[qq*4+3]);
        g_h4[(cb * 4 + q) * DI + d] = make_float4(h[qq*4+0], h[qq*4+1], h[qq*4+2], h[qq*4+3]);
        g_S4[(cb * 4 + q) * DI + d] = make_float4(S[qq*4+0], S[qq*4+1], S[qq*4+2], S[qq*4+3]);
    }
}

// ---------------- K5a: combine 4 chunks -> 1 segment (double-buffered pipeline) ----------------
__global__ void __launch_bounds__(256) k5a_combine()
{
    const int b   = blockIdx.x >> 3;
    const int s   = blockIdx.x & (NSEG - 1);
    const int tid = threadIdx.x;     // channel d
    const int cb0 = b * NCH + s * 4;

    float Pg[16], hg[16], Sg[16];
#pragma unroll
    for (int n = 0; n < 16; n++){ Pg[n] = 1.0f; hg[n] = 0.0f; Sg[n] = 0.0f; }
    float a = 0.0f;

    float  a2[2];
    float4 sv[2][4], pv[2][4], hv[2][4];

    // preload chunk 0
    a2[0] = g_accl[cb0 * DI + tid];
#pragma unroll
    for (int q = 0; q < 4; q++){
        sv[0][q] = g_S4[(cb0 * 4 + q) * DI + tid];
        pv[0][q] = g_P4[(cb0 * 4 + q) * DI + tid];
        hv[0][q] = g_h4[(cb0 * 4 + q) * DI + tid];
    }

#pragma unroll
    for (int ci = 0; ci < 4; ci++){
        const int cur = ci & 1, nxt = cur ^ 1;
        if (ci < 3){
            int cb = cb0 + ci + 1;
            a2[nxt] = g_accl[cb * DI + tid];
#pragma unroll
            for (int q = 0; q < 4; q++){
                sv[nxt][q] = g_S4[(cb * 4 + q) * DI + tid];
                pv[nxt][q] = g_P4[(cb * 4 + q) * DI + tid];
                hv[nxt][q] = g_h4[(cb * 4 + q) * DI + tid];
            }
        }
        a += a2[cur];
#pragma unroll
        for (int q = 0; q < 4; q++){
            a = fmaf(hg[q*4+0], sv[cur][q].x, a);
            a = fmaf(hg[q*4+1], sv[cur][q].y, a);
            a = fmaf(hg[q*4+2], sv[cur][q].z, a);
            a = fmaf(hg[q*4+3], sv[cur][q].w, a);
            Sg[q*4+0] = fmaf(Pg[q*4+0], sv[cur][q].x, Sg[q*4+0]);
            Sg[q*4+1] = fmaf(Pg[q*4+1], sv[cur][q].y, Sg[q*4+1]);
            Sg[q*4+2] = fmaf(Pg[q*4+2], sv[cur][q].z, Sg[q*4+2]);
            Sg[q*4+3] = fmaf(Pg[q*4+3], sv[cur][q].w, Sg[q*4+3]);
            hg[q*4+0] = fmaf(pv[cur][q].x, hg[q*4+0], hv[cur][q].x);
            hg[q*4+1] = fmaf(pv[cur][q].y, hg[q*4+1], hv[cur][q].y);
            hg[q*4+2] = fmaf(pv[cur][q].z, hg[q*4+2], hv[cur][q].z);
            hg[q*4+3] = fmaf(pv[cur][q].w, hg[q*4+3], hv[cur][q].w);
            Pg[q*4+0] *= pv[cur][q].x; Pg[q*4+1] *= pv[cur][q].y;
            Pg[q*4+2] *= pv[cur][q].z; Pg[q*4+3] *= pv[cur][q].w;
        }
    }

    const int sb = b * NSEG + s;
    g_accs[sb * DI + tid] = a;
#pragma unroll
    for (int q = 0; q < 4; q++){
        g_Ps4[(sb * 4 + q) * DI + tid] = make_float4(Pg[q*4+0], Pg[q*4+1], Pg[q*4+2], Pg[q*4+3]);
        g_hs4[(sb * 4 + q) * DI + tid] = make_float4(hg[q*4+0], hg[q*4+1], hg[q*4+2], hg[q*4+3]);
        g_Ss4[(sb * 4 + q) * DI + tid] = make_float4(Sg[q*4+0], Sg[q*4+1], Sg[q*4+2], Sg[q*4+3]);
    }
}

// ---------------- K5b: combine 8 segments (pipelined) + out_proj + mean + classifier ----------------
__global__ void __launch_bounds__(256) k5b_tail(const float* __restrict__ opw,
                                                const float* __restrict__ clw,
                                                const float* __restrict__ clb,
                                                float* __restrict__ out)
{
    __shared__ float sacc[256];
    __shared__ float mvec[128];
    const int b   = blockIdx.x;
    const int tid = threadIdx.x;     // channel d
    const int sb0 = b * NSEG;

    float h[16];
#pragma unroll
    for (int n = 0; n < 16; n++) h[n] = 0.0f;
    float acc = 0.0f;

    float  a2[2];
    float4 sv[2][4], pv[2][4], hv[2][4];

    // preload segment 0
    a2[0] = g_accs[sb0 * DI + tid];
#pragma unroll
    for (int q = 0; q < 4; q++){
        sv[0][q] = g_Ss4[(sb0 * 4 + q) * DI + tid];
        pv[0][q] = g_Ps4[(sb0 * 4 + q) * DI + tid];
        hv[0][q] = g_hs4[(sb0 * 4 + q) * DI + tid];
    }

#pragma unroll
    for (int s = 0; s < NSEG; s++){
        const int cur = s & 1, nxt = cur ^ 1;
        if (s < NSEG - 1){
            int sb = sb0 + s + 1;
            a2[nxt] = g_accs[sb * DI + tid];
#pragma unroll
            for (int q = 0; q < 4; q++){
                sv[nxt][q] = g_Ss4[(sb * 4 + q) * DI + tid];
                pv[nxt][q] = g_Ps4[(sb * 4 + q) * DI + tid];
                hv[nxt][q] = g_hs4[(sb * 4 + q) * DI + tid];
            }
        }
        acc += a2[cur];
#pragma unroll
        for (int q = 0; q < 4; q++){
            acc = fmaf(h[q*4+0], sv[cur][q].x, acc);
            acc = fmaf(h[q*4+1], sv[cur][q].y, acc);
            acc = fmaf(h[q*4+2], sv[cur][q].z, acc);
            acc = fmaf(h[q*4+3], sv[cur][q].w, acc);
            h[q*4+0] = fmaf(pv[cur][q].x, h[q*4+0], hv[cur][q].x);
            h[q*4+1] = fmaf(pv[cur][q].y, h[q*4+1], hv[cur][q].y);
            h[q*4+2] = fmaf(pv[cur][q].z, h[q*4+2], hv[cur][q].z);
            h[q*4+3] = fmaf(pv[cur][q].w, h[q*4+3], hv[cur][q].w);
        }
    }
    sacc[tid] = acc;
    __syncthreads();

    if (tid < 128){
        float s = 0.0f;
#pragma unroll 8
        for (int e = 0; e < 256; e++) s = fmaf(sacc[e], __ldg(opw + tid * 256 + e), s);
        mvec[tid] = s * (1.0f / 2048.0f);
    }
    __syncthreads();
    if (tid < 2){
        float t = __ldg(clb + tid);
#pragma unroll 8
        for (int e = 0; e < 128; e++) t = fmaf(mvec[e], __ldg(clw + tid * 128 + e), t);
        out[b * 2 + tid] = t;
    }
}

// ---------------- launch ----------------
extern "C" void kernel_launch(void* const* d_in, const int* in_sizes, int n_in,
                              void* d_out, int out_size)
{
    const int*   ids  = (const int*)  d_in[0];
    const float* emb  = (const float*)d_in[1];
    const float* ipw  = (const float*)d_in[2];
    const float* cw   = (const float*)d_in[3];
    const float* cb   = (const float*)d_in[4];
    const float* xpw  = (const float*)d_in[5];
    const float* dtw  = (const float*)d_in[6];
    const float* dtb  = (const float*)d_in[7];
    const float* alog = (const float*)d_in[8];
    const float* dvec = (const float*)d_in[9];
    const float* opw  = (const float*)d_in[10];
    const float* clw  = (const float*)d_in[11];
    const float* clb  = (const float*)d_in[12];
    float* out = (float*)d_out;

    dim3 g1(BLn / 128, 4);   // 256 m-tiles x 4 n-tiles of 128
    k1_inproj<<<g1, 256>>>(ids, emb, ipw, cw, cb);
    k3_xproj<<<BLn / 32, 256>>>(xpw, dtw, dtb);
    k4_scan<<<Bsz * NCH * 2, 256>>>(alog, dvec);
    k5a_combine<<<Bsz * NSEG, 256>>>();
    k5b_tail<<<Bsz, 256>>>(opw, clw, clb, out);
}

// round 15
// speedup vs baseline: 1.2607x; 1.0278x over previous
#include <cuda_runtime.h>
#include <math.h>
#include <stdint.h>

// Problem constants
#define Bsz 16
#define Lsz 2048
#define BLn (Bsz*Lsz)          // 32768 (b,l) positions
#define DI 256                 // d_inner
#define DS 16                  // d_state
#define NCH 32                 // scan chunks
#define CLEN (Lsz/NCH)         // 64 steps per chunk
#define NSEG 8                 // segments per batch (4 chunks each)
#define TB3 64                 // K3 tile: bl positions per block

// ---------------- scratch (static device globals; no allocation) ----------------
static __device__ float  g_gate [BLn*DI];   // silu(z)
static __device__ float  g_xc   [BLn*DI];   // silu(conv(x))
static __device__ float2 g_dxc  [BLn*DI];   // packed {delta, xc} from K3
static __device__ float  g_Bm   [BLn*DS];
static __device__ float  g_Cm   [BLn*DS];
// chunk state, channel-fastest float4 quads: [((b*NCH+c)*4+q)*DI + d]
static __device__ float4 g_P4 [Bsz*NCH*4*DI];
static __device__ float4 g_h4 [Bsz*NCH*4*DI];
static __device__ float4 g_S4 [Bsz*NCH*4*DI];
static __device__ float  g_accl[Bsz*NCH*DI];     // [(b*NCH+c)*DI + d]
// segment state (4 chunks combined): [((b*NSEG+s)*4+q)*DI + d]
static __device__ float4 g_Ps4[Bsz*NSEG*4*DI];
static __device__ float4 g_hs4[Bsz*NSEG*4*DI];
static __device__ float4 g_Ss4[Bsz*NSEG*4*DI];
static __device__ float  g_accs[Bsz*NSEG*DI];

__device__ __forceinline__ float silu_f(float x){ return x / (1.0f + __expf(-x)); }
__device__ __forceinline__ float softplus_f(float x){ return (x > 20.0f) ? x : log1pf(__expf(x)); }
__device__ __forceinline__ float to_tf32(float x){
    uint32_t u; asm("cvt.rna.tf32.f32 %0, %1;" : "=r"(u) : "f"(x));
    return __uint_as_float(u);
}

// ---------------- K1: embedding gather + in_proj GEMM (tf32 mma) + FUSED depthwise conv ----------------
// BM=128 x BN=128 (two 64-wide n-subtiles share one A fill). ALL ns loops fully
// unrolled -> static acc indexing.
__global__ void __launch_bounds__(256) k1_inproj(const int* __restrict__ ids,
                                                 const float* __restrict__ emb,
                                                 const float* __restrict__ wproj,
                                                 const float* __restrict__ conv_w,
                                                 const float* __restrict__ conv_b)
{
    __shared__ __align__(16) float smem_all[12288];   // 48 KB
    float* sA = smem_all;           // 8*8*32*4 = 8192 floats (32 KB)
    float* sW = smem_all + 8192;    // 8*8*32*2 = 4096 floats (16 KB)

    const int tid   = threadIdx.x;
    const int lane  = tid & 31;
    const int w     = tid >> 5;
    const int warpM = w >> 1;
    const int warpN = w & 1;
    const int m0     = blockIdx.x * 128;
    const int n_base = blockIdx.y * 128;
    const int l0 = m0 & (Lsz - 1);

    int rid[8];
#pragma unroll
    for (int i = 0; i < 8; i++) rid[i] = ids[m0 + i * 16 + (tid >> 4)];

    float acc[2][2][4][4];
#pragma unroll
    for (int ns = 0; ns < 2; ns++)
#pragma unroll
        for (int mt = 0; mt < 2; mt++)
#pragma unroll
            for (int nt = 0; nt < 4; nt++)
#pragma unroll
                for (int r = 0; r < 4; r++) acc[ns][mt][nt][r] = 0.0f;

#pragma unroll 1
    for (int pass = 0; pass < 2; pass++){
        const int k0 = pass * 64;

        {
            const int kq4 = tid & 15;
#pragma unroll
            for (int i = 0; i < 8; i++){
                int row = i * 16 + (tid >> 4);
                float4 v = *(const float4*)(emb + rid[i] * 128 + k0 + kq4 * 4);
                int base = (((row >> 4) * 8 + (kq4 >> 1)) * 32 + (row & 7) * 4) * 4
                           + ((row >> 3) & 1) + 2 * (kq4 & 1);
                sA[base + 0*4] = to_tf32(v.x);
                sA[base + 1*4] = to_tf32(v.y);
                sA[base + 2*4] = to_tf32(v.z);
                sA[base + 3*4] = to_tf32(v.w);
            }
        }

#pragma unroll
        for (int ns = 0; ns < 2; ns++){
            const int n0 = n_base + ns * 64;
#pragma unroll
            for (int i = 0; i < 4; i++){
                int idx = i * 256 + tid;
                int n   = idx >> 4;
                int kq4 = idx & 15;
                float4 v = *(const float4*)(wproj + (n0 + n) * 128 + k0 + kq4 * 4);
                int base = (((n >> 3) * 8 + (kq4 >> 1)) * 32 + (n & 7) * 4) * 2 + (kq4 & 1);
                sW[base + 0*2] = to_tf32(v.x);
                sW[base + 1*2] = to_tf32(v.y);
                sW[base + 2*2] = to_tf32(v.z);
                sW[base + 3*2] = to_tf32(v.w);
            }
            __syncthreads();

#pragma unroll
            for (int k8 = 0; k8 < 8; k8++){
                float4 af[2];
#pragma unroll
                for (int mt = 0; mt < 2; mt++)
                    af[mt] = *(const float4*)&sA[(((warpM * 2 + mt) * 8 + k8) * 32 + lane) * 4];
                float2 bf[4];
#pragma unroll
                for (int nt = 0; nt < 4; nt++)
                    bf[nt] = *(const float2*)&sW[(((warpN * 4 + nt) * 8 + k8) * 32 + lane) * 2];
#pragma unroll
                for (int mt = 0; mt < 2; mt++)
#pragma unroll
                    for (int nt = 0; nt < 4; nt++){
                        asm volatile(
                            "mma.sync.aligned.m16n8k8.row.col.f32.tf32.tf32.f32 "
                            "{%0,%1,%2,%3},{%4,%5,%6,%7},{%8,%9},{%0,%1,%2,%3};"
                            : "+f"(acc[ns][mt][nt][0]), "+f"(acc[ns][mt][nt][1]),
                              "+f"(acc[ns][mt][nt][2]), "+f"(acc[ns][mt][nt][3])
                            : "r"(__float_as_uint(af[mt].x)), "r"(__float_as_uint(af[mt].y)),
                              "r"(__float_as_uint(af[mt].z)), "r"(__float_as_uint(af[mt].w)),
                              "r"(__float_as_uint(bf[nt].x)), "r"(__float_as_uint(bf[nt].y)));
                    }
            }
            __syncthreads();
        }
    }

    const bool is_x = (n_base < 256);
    float* sE = smem_all;

    if (is_x){
#pragma unroll
        for (int ns = 0; ns < 2; ns++){
            const int n0 = n_base + ns * 64;
#pragma unroll
            for (int mt = 0; mt < 2; mt++)
#pragma unroll
                for (int nt = 0; nt < 4; nt++)
#pragma unroll
                    for (int rh = 0; rh < 2; rh++){
                        int ml = warpM * 32 + mt * 16 + (lane >> 2) + rh * 8;
                        int nl = warpN * 32 + nt * 8 + (lane & 3) * 2;
                        *(float2*)&sE[(ml + 3) * 72 + nl] =
                            make_float2(acc[ns][mt][nt][rh * 2 + 0],
                                        acc[ns][mt][nt][rh * 2 + 1]);
                    }
            if (tid < 192){
                int r  = tid >> 6;
                int ch = tid & 63;
                float s = 0.0f;
                if (l0 != 0){
                    const float4* er = (const float4*)(emb + ids[m0 - 3 + r] * 128);
                    const float4* wr = (const float4*)(wproj + (n0 + ch) * 128);
#pragma unroll 8
                    for (int kk = 0; kk < 32; kk++){
                        float4 e4 = er[kk], w4 = wr[kk];
                        s = fmaf(e4.x, w4.x, s); s = fmaf(e4.y, w4.y, s);
                        s = fmaf(e4.z, w4.z, s); s = fmaf(e4.w, w4.w, s);
                    }
                }
                sE[r * 72 + ch] = s;
            }
            __syncthreads();

            const int q  = tid & 15;
            const int dch = n0 + q * 4;
            float cw[4][4];
#pragma unroll
            for (int cqi = 0; cqi < 4; cqi++){
                float4 wq = __ldg((const float4*)(conv_w + (dch + cqi) * 4));
                cw[cqi][0] = wq.x; cw[cqi][1] = wq.y; cw[cqi][2] = wq.z; cw[cqi][3] = wq.w;
            }
            float4 bb = __ldg((const float4*)(conv_b + dch));
#pragma unroll
            for (int i = 0; i < 8; i++){
                int row = i * 16 + (tid >> 4);
                float4 x0 = *(const float4*)&sE[(row + 0) * 72 + q * 4];
                float4 x1 = *(const float4*)&sE[(row + 1) * 72 + q * 4];
                float4 x2 = *(const float4*)&sE[(row + 2) * 72 + q * 4];
                float4 x3 = *(const float4*)&sE[(row + 3) * 72 + q * 4];
                float a0 = bb.x, a1 = bb.y, a2 = bb.z, a3 = bb.w;
                a0 = fmaf(cw[0][0], x0.x, a0); a1 = fmaf(cw[1][0], x0.y, a1);
                a2 = fmaf(cw[2][0], x0.z, a2); a3 = fmaf(cw[3][0], x0.w, a3);
                a0 = fmaf(cw[0][1], x1.x, a0); a1 = fmaf(cw[1][1], x1.y, a1);
                a2 = fmaf(cw[2][1], x1.z, a2); a3 = fmaf(cw[3][1], x1.w, a3);
                a0 = fmaf(cw[0][2], x2.x, a0); a1 = fmaf(cw[1][2], x2.y, a1);
                a2 = fmaf(cw[2][2], x2.z, a2); a3 = fmaf(cw[3][2], x2.w, a3);
                a0 = fmaf(cw[0][3], x3.x, a0); a1 = fmaf(cw[1][3], x3.y, a1);
                a2 = fmaf(cw[2][3], x3.z, a2); a3 = fmaf(cw[3][3], x3.w, a3);
                float4 o;
                o.x = silu_f(a0); o.y = silu_f(a1); o.z = silu_f(a2); o.w = silu_f(a3);
                *(float4*)(g_xc + (m0 + row) * 256 + dch) = o;
            }
            __syncthreads();
        }
    } else {
#pragma unroll
        for (int ns = 0; ns < 2; ns++){
            const int ncol0 = n_base - 256 + ns * 64;
#pragma unroll
            for (int mt = 0; mt < 2; mt++)
#pragma unroll
                for (int nt = 0; nt < 4; nt++)
#pragma unroll
                    for (int rh = 0; rh < 2; rh++){
                        int ml = warpM * 32 + mt * 16 + (lane >> 2) + rh * 8;
                        int nl = warpN * 32 + nt * 8 + (lane & 3) * 2;
                        *(float2*)&sE[ml * 72 + nl] =
                            make_float2(silu_f(acc[ns][mt][nt][rh * 2 + 0]),
                                        silu_f(acc[ns][mt][nt][rh * 2 + 1]));
                    }
            __syncthreads();
#pragma unroll
            for (int i = 0; i < 8; i++){
                int idx = i * 256 + tid;
                int row = idx >> 4;
                int q   = idx & 15;
                float4 v = *(const float4*)&sE[row * 72 + q * 4];
                *(float4*)(g_gate + (m0 + row) * 256 + ncol0 + q * 4) = v;
            }
            __syncthreads();
        }
    }
}

// ---------------- K3 v2: x_proj via smem-tiled SIMT GEMM (no shuffles) + dt_proj ----------------
// Block: 64 bl positions, 256 threads. Thread computes a 2-bl x 5-j register tile.
// k tiled by 64 (4 tiles). Epilogue: B/C scatter + dt_proj + softplus + {delta,xc} pack.
__global__ void __launch_bounds__(256) k3_xproj(const float* __restrict__ xpw,
                                                const float* __restrict__ dtw,
                                                const float* __restrict__ dtb)
{
    __shared__ __align__(16) float sxc [TB3][68];   // 17.0 KB
    __shared__ __align__(16) float swt [40][68];    // 10.6 KB
    __shared__ float sdbc[TB3][42];                 // 10.5 KB
    const int tid = threadIdx.x;
    const int bl0 = blockIdx.x * TB3;
    const int blg = tid >> 3;        // 0..31 -> bl pair {2*blg, 2*blg+1}
    const int jg  = tid & 7;         // 0..7  -> j set {5*jg .. 5*jg+4}

    float acc[2][5];
#pragma unroll
    for (int b2 = 0; b2 < 2; b2++)
#pragma unroll
        for (int jj = 0; jj < 5; jj++) acc[b2][jj] = 0.0f;

#pragma unroll 1
    for (int kt = 0; kt < 4; kt++){
        const int kk0 = kt * 64;
        // stage xc tile: 64 rows x 64 k
#pragma unroll
        for (int i = 0; i < 4; i++){
            int idx = i * 256 + tid;          // 0..1023
            int r = idx >> 4, c4 = idx & 15;
            float4 v = *(const float4*)(g_xc + (bl0 + r) * 256 + kk0 + c4 * 4);
            *(float4*)&sxc[r][c4 * 4] = v;
        }
        // stage weight tile: 40 rows x 64 k
#pragma unroll
        for (int i = 0; i < 3; i++){
            int idx = i * 256 + tid;          // 0..767 (640 used)
            if (idx < 640){
                int r = idx >> 4, c4 = idx & 15;
                float4 v = __ldg((const float4*)(xpw + r * 256 + kk0 + c4 * 4));
                *(float4*)&swt[r][c4 * 4] = v;
            }
        }
        __syncthreads();

#pragma unroll
        for (int k4 = 0; k4 < 16; k4++){
            float4 x0 = *(const float4*)&sxc[blg * 2 + 0][k4 * 4];
            float4 x1 = *(const float4*)&sxc[blg * 2 + 1][k4 * 4];
#pragma unroll
            for (int jj = 0; jj < 5; jj++){
                float4 wv = *(const float4*)&swt[jg * 5 + jj][k4 * 4];
                acc[0][jj] = fmaf(wv.x, x0.x, acc[0][jj]);
                acc[0][jj] = fmaf(wv.y, x0.y, acc[0][jj]);
                acc[0][jj] = fmaf(wv.z, x0.z, acc[0][jj]);
                acc[0][jj] = fmaf(wv.w, x0.w, acc[0][jj]);
                acc[1][jj] = fmaf(wv.x, x1.x, acc[1][jj]);
                acc[1][jj] = fmaf(wv.y, x1.y, acc[1][jj]);
                acc[1][jj] = fmaf(wv.z, x1.z, acc[1][jj]);
                acc[1][jj] = fmaf(wv.w, x1.w, acc[1][jj]);
            }
        }
        __syncthreads();
    }

    // scatter register tile into sdbc
#pragma unroll
    for (int b2 = 0; b2 < 2; b2++)
#pragma unroll
        for (int jj = 0; jj < 5; jj++)
            sdbc[blg * 2 + b2][jg * 5 + jj] = acc[b2][jj];
    __syncthreads();

    // B/C: 64 bl x 16 each
#pragma unroll
    for (int q = 0; q < 4; q++){
        int idx = tid * 4 + q;        // 0..1023
        int bl = idx >> 4, n = idx & 15;
        g_Bm[(bl0 + bl) * 16 + n] = sdbc[bl][8 + n];
        g_Cm[(bl0 + bl) * 16 + n] = sdbc[bl][24 + n];
    }

    // dt_proj + softplus + {delta,xc} pack: thread = channel d
    {
        const int d = tid;
        float4 w0 = __ldg((const float4*)(dtw + d * 8));
        float4 w1 = __ldg((const float4*)(dtw + d * 8 + 4));
        float bias = __ldg(dtb + d);
#pragma unroll 4
        for (int bl = 0; bl < TB3; bl++){
            const float* dv = sdbc[bl];
            float t = bias;
            t = fmaf(w0.x, dv[0], t); t = fmaf(w0.y, dv[1], t);
            t = fmaf(w0.z, dv[2], t); t = fmaf(w0.w, dv[3], t);
            t = fmaf(w1.x, dv[4], t); t = fmaf(w1.y, dv[5], t);
            t = fmaf(w1.z, dv[6], t); t = fmaf(w1.w, dv[7], t);
            float xc = g_xc[(bl0 + bl) * 256 + d];
            g_dxc[(bl0 + bl) * 256 + d] = make_float2(softplus_f(t), xc);
        }
    }
}

// ---------------- K4: chunked selective scan, pass A ----------------
__global__ void __launch_bounds__(256, 3) k4_scan(const float* __restrict__ A_log,
                                                  const float* __restrict__ Dvec)
{
    __shared__ __align__(16) float sB[CLEN * 16];
    __shared__ __align__(16) float sC[CLEN * 16];
    __shared__ float sacc[128];

    const int b   = blockIdx.x >> 6;
    const int c   = (blockIdx.x >> 1) & 31;
    const int hb  = blockIdx.x & 1;
    const int tid = threadIdx.x;
    const int sh  = tid >> 7;
    const int dl  = tid & 127;
    const int d   = hb * 128 + dl;
    const int n0  = sh * 8;

    const float An0 = -__expf(__ldg(A_log + d * 16));
    bool pw_ok = true;
#pragma unroll
    for (int j = 0; j < 8; j++){
        float Ann = -__expf(__ldg(A_log + d * 16 + n0 + j));
        pw_ok = pw_ok && (fabsf(Ann / An0 - (float)(n0 + j + 1)) < 1e-3f);
    }
    const float Dd_eff = sh ? 0.0f : __ldg(Dvec + d);

    const int l0 = b * Lsz + c * CLEN;
    {
        const float4* gB = (const float4*)(g_Bm + l0 * 16);
        const float4* gC4 = (const float4*)(g_Cm + l0 * 16);
        ((float4*)sB)[tid] = gB[tid];
        ((float4*)sC)[tid] = gC4[tid];
    }
    __syncthreads();

    float h[8], P[8], S[8];
#pragma unroll
    for (int j = 0; j < 8; j++){ h[j] = 0.0f; P[j] = 1.0f; S[j] = 0.0f; }
    float accl = 0.0f;

    int base = l0 * 256 + d;

    if (pw_ok){
        float2 pdx[4]; float pg[4];
#pragma unroll
        for (int q = 0; q < 4; q++){
            pdx[q] = g_dxc[base + q * 256];
            pg[q]  = __ldg(g_gate + base + q * 256);
        }
#pragma unroll 1
        for (int t = 0; t < CLEN; t += 4){
            float2 cdx[4]; float cg[4];
#pragma unroll
            for (int q = 0; q < 4; q++){ cdx[q] = pdx[q]; cg[q] = pg[q]; }
            int nb = base + 4 * 256;
            if (t + 4 < CLEN){
#pragma unroll
                for (int q = 0; q < 4; q++){
                    pdx[q] = g_dxc[nb + q * 256];
                    pg[q]  = __ldg(g_gate + nb + q * 256);
                }
            }
            float e1v[4];
#pragma unroll
            for (int q = 0; q < 4; q++) e1v[q] = __expf(cdx[q].x * An0);

#pragma unroll
            for (int q = 0; q < 4; q++){
                float gv  = cg[q];
                float xcv = cdx[q].y;
                float dxv = cdx[q].x * xcv;

                float qp[8];
                qp[0] = e1v[q];
#pragma unroll
                for (int i = 1; i < 8; i++) qp[i] = qp[(i - 1) >> 1] * qp[i >> 1];
                if (sh){
                    float e8 = qp[7];
#pragma unroll
                    for (int j = 0; j < 8; j++) qp[j] *= e8;
                }

                float4 bb0 = ((const float4*)sB)[(t + q) * 4 + sh * 2 + 0];
                float4 bb1 = ((const float4*)sB)[(t + q) * 4 + sh * 2 + 1];
                float4 cc0 = ((const float4*)sC)[(t + q) * 4 + sh * 2 + 0];
                float4 cc1 = ((const float4*)sC)[(t + q) * 4 + sh * 2 + 1];
                float Bv[8] = {bb0.x, bb0.y, bb0.z, bb0.w, bb1.x, bb1.y, bb1.z, bb1.w};
                float gC[8] = {gv*cc0.x, gv*cc0.y, gv*cc0.z, gv*cc0.w,
                               gv*cc1.x, gv*cc1.y, gv*cc1.z, gv*cc1.w};

#pragma unroll
                for (int j = 0; j < 8; j++){
                    P[j] *= qp[j];
                    h[j] = fmaf(qp[j], h[j], dxv * Bv[j]);
                    accl = fmaf(h[j], gC[j], accl);
                    S[j] = fmaf(P[j], gC[j], S[j]);
                }
                accl = fmaf(gv * xcv, Dd_eff, accl);
            }
            base = nb;
        }
    } else {
#pragma unroll 1
        for (int t = 0; t < CLEN; t++){
            float2 dxc  = g_dxc[base];
            float delta = dxc.x;
            float xcv   = dxc.y;
            float gv    = g_gate[base];
            float dxv   = delta * xcv;
#pragma unroll 4
            for (int j = 0; j < 8; j++){
                float An = -__expf(__ldg(A_log + d * 16 + n0 + j));
                float dA = __expf(delta * An);
                float Bn = sB[t * 16 + n0 + j];
                float Cn = sC[t * 16 + n0 + j] * gv;
                P[j] *= dA;
                h[j] = fmaf(dA, h[j], dxv * Bn);
                accl = fmaf(h[j], Cn, accl);
                S[j] = fmaf(P[j], Cn, S[j]);
            }
            accl = fmaf(gv * xcv, Dd_eff, accl);
            base += 256;
        }
    }

    if (sh) sacc[dl] = accl;
    __syncthreads();

    const int cb = b * NCH + c;
    if (!sh) g_accl[cb * DI + d] = accl + sacc[dl];
#pragma unroll
    for (int qq = 0; qq < 2; qq++){
        int q = sh * 2 + qq;
        g_P4[(cb * 4 + q) * DI + d] = make_float4(P[qq*4+0], P[qq*4+1], P[qq*4+2], P[qq*4+3]);
        g_h4[(cb * 4 + q) * DI + d] = make_float4(h[qq*4+0], h[qq*4+1], h[qq*4+2], h[qq*4+3]);
        g_S4[(cb * 4 + q) * DI + d] = make_float4(S[qq*4+0], S[qq*4+1], S[qq*4+2], S[qq*4+3]);
    }
}

// ---------------- K5a: combine 4 chunks -> 1 segment ----------------
__global__ void __launch_bounds__(256) k5a_combine()
{
    const int b   = blockIdx.x >> 3;
    const int s   = blockIdx.x & (NSEG - 1);
    const int tid = threadIdx.x;
    const int cb0 = b * NCH + s * 4;

    float Pg[16], hg[16], Sg[16];
#pragma unroll
    for (int n = 0; n < 16; n++){ Pg[n] = 1.0f; hg[n] = 0.0f; Sg[n] = 0.0f; }
    float a = 0.0f;

    float  a2[2];
    float4 sv[2][4], pv[2][4], hv[2][4];

    a2[0] = g_accl[cb0 * DI + tid];
#pragma unroll
    for (int q = 0; q < 4; q++){
        sv[0][q] = g_S4[(cb0 * 4 + q) * DI + tid];
        pv[0][q] = g_P4[(cb0 * 4 + q) * DI + tid];
        hv[0][q] = g_h4[(cb0 * 4 + q) * DI + tid];
    }

#pragma unroll
    for (int ci = 0; ci < 4; ci++){
        const int cur = ci & 1, nxt = cur ^ 1;
        if (ci < 3){
            int cb = cb0 + ci + 1;
            a2[nxt] = g_accl[cb * DI + tid];
#pragma unroll
            for (int q = 0; q < 4; q++){
                sv[nxt][q] = g_S4[(cb * 4 + q) * DI + tid];
                pv[nxt][q] = g_P4[(cb * 4 + q) * DI + tid];
                hv[nxt][q] = g_h4[(cb * 4 + q) * DI + tid];
            }
        }
        a += a2[cur];
#pragma unroll
        for (int q = 0; q < 4; q++){
            a = fmaf(hg[q*4+0], sv[cur][q].x, a);
            a = fmaf(hg[q*4+1], sv[cur][q].y, a);
            a = fmaf(hg[q*4+2], sv[cur][q].z, a);
            a = fmaf(hg[q*4+3], sv[cur][q].w, a);
            Sg[q*4+0] = fmaf(Pg[q*4+0], sv[cur][q].x, Sg[q*4+0]);
            Sg[q*4+1] = fmaf(Pg[q*4+1], sv[cur][q].y, Sg[q*4+1]);
            Sg[q*4+2] = fmaf(Pg[q*4+2], sv[cur][q].z, Sg[q*4+2]);
            Sg[q*4+3] = fmaf(Pg[q*4+3], sv[cur][q].w, Sg[q*4+3]);
            hg[q*4+0] = fmaf(pv[cur][q].x, hg[q*4+0], hv[cur][q].x);
            hg[q*4+1] = fmaf(pv[cur][q].y, hg[q*4+1], hv[cur][q].y);
            hg[q*4+2] = fmaf(pv[cur][q].z, hg[q*4+2], hv[cur][q].z);
            hg[q*4+3] = fmaf(pv[cur][q].w, hg[q*4+3], hv[cur][q].w);
            Pg[q*4+0] *= pv[cur][q].x; Pg[q*4+1] *= pv[cur][q].y;
            Pg[q*4+2] *= pv[cur][q].z; Pg[q*4+3] *= pv[cur][q].w;
        }
    }

    const int sb = b * NSEG + s;
    g_accs[sb * DI + tid] = a;
#pragma unroll
    for (int q = 0; q < 4; q++){
        g_Ps4[(sb * 4 + q) * DI + tid] = make_float4(Pg[q*4+0], Pg[q*4+1], Pg[q*4+2], Pg[q*4+3]);
        g_hs4[(sb * 4 + q) * DI + tid] = make_float4(hg[q*4+0], hg[q*4+1], hg[q*4+2], hg[q*4+3]);
        g_Ss4[(sb * 4 + q) * DI + tid] = make_float4(Sg[q*4+0], Sg[q*4+1], Sg[q*4+2], Sg[q*4+3]);
    }
}

// ---------------- K5b: combine 8 segments + out_proj + mean + classifier ----------------
__global__ void __launch_bounds__(256) k5b_tail(const float* __restrict__ opw,
                                                const float* __restrict__ clw,
                                                const float* __restrict__ clb,
                                                float* __restrict__ out)
{
    __shared__ float sacc[256];
    __shared__ float mvec[128];
    const int b   = blockIdx.x;
    const int tid = threadIdx.x;
    const int sb0 = b * NSEG;

    float h[16];
#pragma unroll
    for (int n = 0; n < 16; n++) h[n] = 0.0f;
    float acc = 0.0f;

    float  a2[2];
    float4 sv[2][4], pv[2][4], hv[2][4];

    a2[0] = g_accs[sb0 * DI + tid];
#pragma unroll
    for (int q = 0; q < 4; q++){
        sv[0][q] = g_Ss4[(sb0 * 4 + q) * DI + tid];
        pv[0][q] = g_Ps4[(sb0 * 4 + q) * DI + tid];
        hv[0][q] = g_hs4[(sb0 * 4 + q) * DI + tid];
    }

#pragma unroll
    for (int s = 0; s < NSEG; s++){
        const int cur = s & 1, nxt = cur ^ 1;
        if (s < NSEG - 1){
            int sb = sb0 + s + 1;
            a2[nxt] = g_accs[sb * DI + tid];
#pragma unroll
            for (int q = 0; q < 4; q++){
                sv[nxt][q] = g_Ss4[(sb * 4 + q) * DI + tid];
                pv[nxt][q] = g_Ps4[(sb * 4 + q) * DI + tid];
                hv[nxt][q] = g_hs4[(sb * 4 + q) * DI + tid];
            }
        }
        acc += a2[cur];
#pragma unroll
        for (int q = 0; q < 4; q++){
            acc = fmaf(h[q*4+0], sv[cur][q].x, acc);
            acc = fmaf(h[q*4+1], sv[cur][q].y, acc);
            acc = fmaf(h[q*4+2], sv[cur][q].z, acc);
            acc = fmaf(h[q*4+3], sv[cur][q].w, acc);
            h[q*4+0] = fmaf(pv[cur][q].x, h[q*4+0], hv[cur][q].x);
            h[q*4+1] = fmaf(pv[cur][q].y, h[q*4+1], hv[cur][q].y);
            h[q*4+2] = fmaf(pv[cur][q].z, h[q*4+2], hv[cur][q].z);
            h[q*4+3] = fmaf(pv[cur][q].w, h[q*4+3], hv[cur][q].w);
        }
    }
    sacc[tid] = acc;
    __syncthreads();

    if (tid < 128){
        float s = 0.0f;
#pragma unroll 8
        for (int e = 0; e < 256; e++) s = fmaf(sacc[e], __ldg(opw + tid * 256 + e), s);
        mvec[tid] = s * (1.0f / 2048.0f);
    }
    __syncthreads();
    if (tid < 2){
        float t = __ldg(clb + tid);
#pragma unroll 8
        for (int e = 0; e < 128; e++) t = fmaf(mvec[e], __ldg(clw + tid * 128 + e), t);
        out[b * 2 + tid] = t;
    }
}

// ---------------- launch ----------------
extern "C" void kernel_launch(void* const* d_in, const int* in_sizes, int n_in,
                              void* d_out, int out_size)
{
    const int*   ids  = (const int*)  d_in[0];
    const float* emb  = (const float*)d_in[1];
    const float* ipw  = (const float*)d_in[2];
    const float* cw   = (const float*)d_in[3];
    const float* cb   = (const float*)d_in[4];
    const float* xpw  = (const float*)d_in[5];
    const float* dtw  = (const float*)d_in[6];
    const float* dtb  = (const float*)d_in[7];
    const float* alog = (const float*)d_in[8];
    const float* dvec = (const float*)d_in[9];
    const float* opw  = (const float*)d_in[10];
    const float* clw  = (const float*)d_in[11];
    const float* clb  = (const float*)d_in[12];
    float* out = (float*)d_out;

    dim3 g1(BLn / 128, 4);   // 256 m-tiles x 4 n-tiles of 128
    k1_inproj<<<g1, 256>>>(ids, emb, ipw, cw, cb);
    k3_xproj<<<BLn / TB3, 256>>>(xpw, dtw, dtb);
    k4_scan<<<Bsz * NCH * 2, 256>>>(alog, dvec);
    k5a_combine<<<Bsz * NSEG, 256>>>();
    k5b_tail<<<Bsz, 256>>>(opw, clw, clb, out);
}

// round 17
// speedup vs baseline: 1.2995x; 1.0307x over previous
#include <cuda_runtime.h>
#include <math.h>
#include <stdint.h>

// Problem constants
#define Bsz 16
#define Lsz 2048
#define BLn (Bsz*Lsz)          // 32768 (b,l) positions
#define DI 256                 // d_inner
#define DS 16                  // d_state
#define NCH 32                 // scan chunks
#define CLEN (Lsz/NCH)         // 64 steps per chunk
#define NSEG 8                 // segments per batch (4 chunks each)
#define TB3 64                 // K3 tile: bl positions per block

// ---------------- scratch (static device globals; no allocation) ----------------
static __device__ float  g_gate [BLn*DI];   // silu(z)
static __device__ float  g_xc   [BLn*DI];   // silu(conv(x))
static __device__ float2 g_dxc  [BLn*DI];   // packed {delta, xc} from K3
static __device__ float  g_Bm   [BLn*DS];
static __device__ float  g_Cm   [BLn*DS];
// chunk state, channel-fastest float4 quads: [((b*NCH+c)*4+q)*DI + d]
static __device__ float4 g_P4 [Bsz*NCH*4*DI];
static __device__ float4 g_h4 [Bsz*NCH*4*DI];
static __device__ float4 g_S4 [Bsz*NCH*4*DI];
static __device__ float  g_accl[Bsz*NCH*DI];     // [(b*NCH+c)*DI + d]
// segment state (4 chunks combined): [((b*NSEG+s)*4+q)*DI + d]
static __device__ float4 g_Ps4[Bsz*NSEG*4*DI];
static __device__ float4 g_hs4[Bsz*NSEG*4*DI];
static __device__ float4 g_Ss4[Bsz*NSEG*4*DI];
static __device__ float  g_accs[Bsz*NSEG*DI];

// fast-math intrinsics regardless of compile flags:
// silu via MUFU.EX2 + MUFU.RCP (no IEEE divide), softplus via MUFU.LG2 (no libm log1pf)
__device__ __forceinline__ float silu_f(float x){
    return __fdividef(x, 1.0f + __expf(-x));
}
__device__ __forceinline__ float softplus_f(float x){
    return (x > 20.0f) ? x : __logf(1.0f + __expf(x));
}
__device__ __forceinline__ float to_tf32(float x){
    uint32_t u; asm("cvt.rna.tf32.f32 %0, %1;" : "=r"(u) : "f"(x));
    return __uint_as_float(u);
}

// ---------------- K1: embedding gather + in_proj GEMM (tf32 mma) + FUSED depthwise conv ----------------
// BM=128 x BN=128 (two 64-wide n-subtiles share one A fill). ALL ns loops fully
// unrolled -> static acc indexing.
__global__ void __launch_bounds__(256) k1_inproj(const int* __restrict__ ids,
                                                 const float* __restrict__ emb,
                                                 const float* __restrict__ wproj,
                                                 const float* __restrict__ conv_w,
                                                 const float* __restrict__ conv_b)
{
    __shared__ __align__(16) float smem_all[12288];   // 48 KB
    float* sA = smem_all;           // 8*8*32*4 = 8192 floats (32 KB)
    float* sW = smem_all + 8192;    // 8*8*32*2 = 4096 floats (16 KB)

    const int tid   = threadIdx.x;
    const int lane  = tid & 31;
    const int w     = tid >> 5;
    const int warpM = w >> 1;
    const int warpN = w & 1;
    const int m0     = blockIdx.x * 128;
    const int n_base = blockIdx.y * 128;
    const int l0 = m0 & (Lsz - 1);

    int rid[8];
#pragma unroll
    for (int i = 0; i < 8; i++) rid[i] = ids[m0 + i * 16 + (tid >> 4)];

    float acc[2][2][4][4];
#pragma unroll
    for (int ns = 0; ns < 2; ns++)
#pragma unroll
        for (int mt = 0; mt < 2; mt++)
#pragma unroll
            for (int nt = 0; nt < 4; nt++)
#pragma unroll
                for (int r = 0; r < 4; r++) acc[ns][mt][nt][r] = 0.0f;

#pragma unroll 1
    for (int pass = 0; pass < 2; pass++){
        const int k0 = pass * 64;

        {
            const int kq4 = tid & 15;
#pragma unroll
            for (int i = 0; i < 8; i++){
                int row = i * 16 + (tid >> 4);
                float4 v = *(const float4*)(emb + rid[i] * 128 + k0 + kq4 * 4);
                int base = (((row >> 4) * 8 + (kq4 >> 1)) * 32 + (row & 7) * 4) * 4
                           + ((row >> 3) & 1) + 2 * (kq4 & 1);
                sA[base + 0*4] = to_tf32(v.x);
                sA[base + 1*4] = to_tf32(v.y);
                sA[base + 2*4] = to_tf32(v.z);
                sA[base + 3*4] = to_tf32(v.w);
            }
        }

#pragma unroll
        for (int ns = 0; ns < 2; ns++){
            const int n0 = n_base + ns * 64;
#pragma unroll
            for (int i = 0; i < 4; i++){
                int idx = i * 256 + tid;
                int n   = idx >> 4;
                int kq4 = idx & 15;
                float4 v = *(const float4*)(wproj + (n0 + n) * 128 + k0 + kq4 * 4);
                int base = (((n >> 3) * 8 + (kq4 >> 1)) * 32 + (n & 7) * 4) * 2 + (kq4 & 1);
                sW[base + 0*2] = to_tf32(v.x);
                sW[base + 1*2] = to_tf32(v.y);
                sW[base + 2*2] = to_tf32(v.z);
                sW[base + 3*2] = to_tf32(v.w);
            }
            __syncthreads();

#pragma unroll
            for (int k8 = 0; k8 < 8; k8++){
                float4 af[2];
#pragma unroll
                for (int mt = 0; mt < 2; mt++)
                    af[mt] = *(const float4*)&sA[(((warpM * 2 + mt) * 8 + k8) * 32 + lane) * 4];
                float2 bf[4];
#pragma unroll
                for (int nt = 0; nt < 4; nt++)
                    bf[nt] = *(const float2*)&sW[(((warpN * 4 + nt) * 8 + k8) * 32 + lane) * 2];
#pragma unroll
                for (int mt = 0; mt < 2; mt++)
#pragma unroll
                    for (int nt = 0; nt < 4; nt++){
                        asm volatile(
                            "mma.sync.aligned.m16n8k8.row.col.f32.tf32.tf32.f32 "
                            "{%0,%1,%2,%3},{%4,%5,%6,%7},{%8,%9},{%0,%1,%2,%3};"
                            : "+f"(acc[ns][mt][nt][0]), "+f"(acc[ns][mt][nt][1]),
                              "+f"(acc[ns][mt][nt][2]), "+f"(acc[ns][mt][nt][3])
                            : "r"(__float_as_uint(af[mt].x)), "r"(__float_as_uint(af[mt].y)),
                              "r"(__float_as_uint(af[mt].z)), "r"(__float_as_uint(af[mt].w)),
                              "r"(__float_as_uint(bf[nt].x)), "r"(__float_as_uint(bf[nt].y)));
                    }
            }
            __syncthreads();
        }
    }

    const bool is_x = (n_base < 256);
    float* sE = smem_all;

    if (is_x){
#pragma unroll
        for (int ns = 0; ns < 2; ns++){
            const int n0 = n_base + ns * 64;
#pragma unroll
            for (int mt = 0; mt < 2; mt++)
#pragma unroll
                for (int nt = 0; nt < 4; nt++)
#pragma unroll
                    for (int rh = 0; rh < 2; rh++){
                        int ml = warpM * 32 + mt * 16 + (lane >> 2) + rh * 8;
                        int nl = warpN * 32 + nt * 8 + (lane & 3) * 2;
                        *(float2*)&sE[(ml + 3) * 72 + nl] =
                            make_float2(acc[ns][mt][nt][rh * 2 + 0],
                                        acc[ns][mt][nt][rh * 2 + 1]);
                    }
            if (tid < 192){
                int r  = tid >> 6;
                int ch = tid & 63;
                float s = 0.0f;
                if (l0 != 0){
                    const float4* er = (const float4*)(emb + ids[m0 - 3 + r] * 128);
                    const float4* wr = (const float4*)(wproj + (n0 + ch) * 128);
#pragma unroll 8
                    for (int kk = 0; kk < 32; kk++){
                        float4 e4 = er[kk], w4 = wr[kk];
                        s = fmaf(e4.x, w4.x, s); s = fmaf(e4.y, w4.y, s);
                        s = fmaf(e4.z, w4.z, s); s = fmaf(e4.w, w4.w, s);
                    }
                }
                sE[r * 72 + ch] = s;
            }
            __syncthreads();

            const int q  = tid & 15;
            const int dch = n0 + q * 4;
            float cw[4][4];
#pragma unroll
            for (int cqi = 0; cqi < 4; cqi++){
                float4 wq = __ldg((const float4*)(conv_w + (dch + cqi) * 4));
                cw[cqi][0] = wq.x; cw[cqi][1] = wq.y; cw[cqi][2] = wq.z; cw[cqi][3] = wq.w;
            }
            float4 bb = __ldg((const float4*)(conv_b + dch));
#pragma unroll
            for (int i = 0; i < 8; i++){
                int row = i * 16 + (tid >> 4);
                float4 x0 = *(const float4*)&sE[(row + 0) * 72 + q * 4];
                float4 x1 = *(const float4*)&sE[(row + 1) * 72 + q * 4];
                float4 x2 = *(const float4*)&sE[(row + 2) * 72 + q * 4];
                float4 x3 = *(const float4*)&sE[(row + 3) * 72 + q * 4];
                float a0 = bb.x, a1 = bb.y, a2 = bb.z, a3 = bb.w;
                a0 = fmaf(cw[0][0], x0.x, a0); a1 = fmaf(cw[1][0], x0.y, a1);
                a2 = fmaf(cw[2][0], x0.z, a2); a3 = fmaf(cw[3][0], x0.w, a3);
                a0 = fmaf(cw[0][1], x1.x, a0); a1 = fmaf(cw[1][1], x1.y, a1);
                a2 = fmaf(cw[2][1], x1.z, a2); a3 = fmaf(cw[3][1], x1.w, a3);
                a0 = fmaf(cw[0][2], x2.x, a0); a1 = fmaf(cw[1][2], x2.y, a1);
                a2 = fmaf(cw[2][2], x2.z, a2); a3 = fmaf(cw[3][2], x2.w, a3);
                a0 = fmaf(cw[0][3], x3.x, a0); a1 = fmaf(cw[1][3], x3.y, a1);
                a2 = fmaf(cw[2][3], x3.z, a2); a3 = fmaf(cw[3][3], x3.w, a3);
                float4 o;
                o.x = silu_f(a0); o.y = silu_f(a1); o.z = silu_f(a2); o.w = silu_f(a3);
                *(float4*)(g_xc + (m0 + row) * 256 + dch) = o;
            }
            __syncthreads();
        }
    } else {
#pragma unroll
        for (int ns = 0; ns < 2; ns++){
            const int ncol0 = n_base - 256 + ns * 64;
#pragma unroll
            for (int mt = 0; mt < 2; mt++)
#pragma unroll
                for (int nt = 0; nt < 4; nt++)
#pragma unroll
                    for (int rh = 0; rh < 2; rh++){
                        int ml = warpM * 32 + mt * 16 + (lane >> 2) + rh * 8;
                        int nl = warpN * 32 + nt * 8 + (lane & 3) * 2;
                        *(float2*)&sE[ml * 72 + nl] =
                            make_float2(silu_f(acc[ns][mt][nt][rh * 2 + 0]),
                                        silu_f(acc[ns][mt][nt][rh * 2 + 1]));
                    }
            __syncthreads();
#pragma unroll
            for (int i = 0; i < 8; i++){
                int idx = i * 256 + tid;
                int row = idx >> 4;
                int q   = idx & 15;
                float4 v = *(const float4*)&sE[row * 72 + q * 4];
                *(float4*)(g_gate + (m0 + row) * 256 + ncol0 + q * 4) = v;
            }
            __syncthreads();
        }
    }
}

// ---------------- K3 v2: x_proj via smem-tiled SIMT GEMM (no shuffles) + dt_proj ----------------
__global__ void __launch_bounds__(256) k3_xproj(const float* __restrict__ xpw,
                                                const float* __restrict__ dtw,
                                                const float* __restrict__ dtb)
{
    __shared__ __align__(16) float sxc [TB3][68];   // 17.0 KB
    __shared__ __align__(16) float swt [40][68];    // 10.6 KB
    __shared__ float sdbc[TB3][42];                 // 10.5 KB
    const int tid = threadIdx.x;
    const int bl0 = blockIdx.x * TB3;
    const int blg = tid >> 3;        // 0..31 -> bl pair {2*blg, 2*blg+1}
    const int jg  = tid & 7;         // 0..7  -> j set {5*jg .. 5*jg+4}

    float acc[2][5];
#pragma unroll
    for (int b2 = 0; b2 < 2; b2++)
#pragma unroll
        for (int jj = 0; jj < 5; jj++) acc[b2][jj] = 0.0f;

#pragma unroll 1
    for (int kt = 0; kt < 4; kt++){
        const int kk0 = kt * 64;
#pragma unroll
        for (int i = 0; i < 4; i++){
            int idx = i * 256 + tid;
            int r = idx >> 4, c4 = idx & 15;
            float4 v = *(const float4*)(g_xc + (bl0 + r) * 256 + kk0 + c4 * 4);
            *(float4*)&sxc[r][c4 * 4] = v;
        }
#pragma unroll
        for (int i = 0; i < 3; i++){
            int idx = i * 256 + tid;
            if (idx < 640){
                int r = idx >> 4, c4 = idx & 15;
                float4 v = __ldg((const float4*)(xpw + r * 256 + kk0 + c4 * 4));
                *(float4*)&swt[r][c4 * 4] = v;
            }
        }
        __syncthreads();

#pragma unroll
        for (int k4 = 0; k4 < 16; k4++){
            float4 x0 = *(const float4*)&sxc[blg * 2 + 0][k4 * 4];
            float4 x1 = *(const float4*)&sxc[blg * 2 + 1][k4 * 4];
#pragma unroll
            for (int jj = 0; jj < 5; jj++){
                float4 wv = *(const float4*)&swt[jg * 5 + jj][k4 * 4];
                acc[0][jj] = fmaf(wv.x, x0.x, acc[0][jj]);
                acc[0][jj] = fmaf(wv.y, x0.y, acc[0][jj]);
                acc[0][jj] = fmaf(wv.z, x0.z, acc[0][jj]);
                acc[0][jj] = fmaf(wv.w, x0.w, acc[0][jj]);
                acc[1][jj] = fmaf(wv.x, x1.x, acc[1][jj]);
                acc[1][jj] = fmaf(wv.y, x1.y, acc[1][jj]);
                acc[1][jj] = fmaf(wv.z, x1.z, acc[1][jj]);
                acc[1][jj] = fmaf(wv.w, x1.w, acc[1][jj]);
            }
        }
        __syncthreads();
    }

#pragma unroll
    for (int b2 = 0; b2 < 2; b2++)
#pragma unroll
        for (int jj = 0; jj < 5; jj++)
            sdbc[blg * 2 + b2][jg * 5 + jj] = acc[b2][jj];
    __syncthreads();

#pragma unroll
    for (int q = 0; q < 4; q++){
        int idx = tid * 4 + q;
        int bl = idx >> 4, n = idx & 15;
        g_Bm[(bl0 + bl) * 16 + n] = sdbc[bl][8 + n];
        g_Cm[(bl0 + bl) * 16 + n] = sdbc[bl][24 + n];
    }

    {
        const int d = tid;
        float4 w0 = __ldg((const float4*)(dtw + d * 8));
        float4 w1 = __ldg((const float4*)(dtw + d * 8 + 4));
        float bias = __ldg(dtb + d);
#pragma unroll 4
        for (int bl = 0; bl < TB3; bl++){
            const float* dv = sdbc[bl];
            float t = bias;
            t = fmaf(w0.x, dv[0], t); t = fmaf(w0.y, dv[1], t);
            t = fmaf(w0.z, dv[2], t); t = fmaf(w0.w, dv[3], t);
            t = fmaf(w1.x, dv[4], t); t = fmaf(w1.y, dv[5], t);
            t = fmaf(w1.z, dv[6], t); t = fmaf(w1.w, dv[7], t);
            float xc = g_xc[(bl0 + bl) * 256 + d];
            g_dxc[(bl0 + bl) * 256 + d] = make_float2(softplus_f(t), xc);
        }
    }
}

// ---------------- K4: chunked selective scan, pass A ----------------
__global__ void __launch_bounds__(256, 3) k4_scan(const float* __restrict__ A_log,
                                                  const float* __restrict__ Dvec)
{
    __shared__ __align__(16) float sB[CLEN * 16];
    __shared__ __align__(16) float sC[CLEN * 16];
    __shared__ float sacc[128];

    const int b   = blockIdx.x >> 6;
    const int c   = (blockIdx.x >> 1) & 31;
    const int hb  = blockIdx.x & 1;
    const int tid = threadIdx.x;
    const int sh  = tid >> 7;
    const int dl  = tid & 127;
    const int d   = hb * 128 + dl;
    const int n0  = sh * 8;

    const float An0 = -__expf(__ldg(A_log + d * 16));
    bool pw_ok = true;
#pragma unroll
    for (int j = 0; j < 8; j++){
        float Ann = -__expf(__ldg(A_log + d * 16 + n0 + j));
        pw_ok = pw_ok && (fabsf(Ann / An0 - (float)(n0 + j + 1)) < 1e-3f);
    }
    const float Dd = __ldg(Dvec + d);

    const int l0 = b * Lsz + c * CLEN;
    {
        const float4* gB = (const float4*)(g_Bm + l0 * 16);
        const float4* gC4 = (const float4*)(g_Cm + l0 * 16);
        ((float4*)sB)[tid] = gB[tid];
        ((float4*)sC)[tid] = gC4[tid];
    }
    __syncthreads();

    float h[8], P[8], S[8];
#pragma unroll
    for (int j = 0; j < 8; j++){ h[j] = 0.0f; P[j] = 1.0f; S[j] = 0.0f; }
    float accl = 0.0f;

    int base = l0 * 256 + d;

    if (pw_ok){
        float2 pdx[4]; float pg[4];
#pragma unroll
        for (int q = 0; q < 4; q++){
            pdx[q] = g_dxc[base + q * 256];
            pg[q]  = __ldg(g_gate + base + q * 256);
        }
#pragma unroll 1
        for (int t = 0; t < CLEN; t += 4){
            float2 cdx[4]; float cg[4];
#pragma unroll
            for (int q = 0; q < 4; q++){ cdx[q] = pdx[q]; cg[q] = pg[q]; }
            int nb = base + 4 * 256;
            if (t + 4 < CLEN){
#pragma unroll
                for (int q = 0; q < 4; q++){
                    pdx[q] = g_dxc[nb + q * 256];
                    pg[q]  = __ldg(g_gate + nb + q * 256);
                }
            }
            float e1v[4];
#pragma unroll
            for (int q = 0; q < 4; q++) e1v[q] = __expf(cdx[q].x * An0);

#pragma unroll
            for (int q = 0; q < 4; q++){
                float gv  = cg[q];
                float xcv = cdx[q].y;
                float dxv = cdx[q].x * xcv;

                float qp[8];
                if (!sh){
                    // e1^1..e1^8 (7 mults)
                    qp[0] = e1v[q];
#pragma unroll
                    for (int i = 1; i < 8; i++) qp[i] = qp[(i - 1) >> 1] * qp[i >> 1];
                } else {
                    // e1^9..e1^16 via squarings (3) + 8 mults
                    float e1 = e1v[q];
                    float e2 = e1 * e1, e4 = e2 * e2, e8 = e4 * e4;
                    qp[0] = e8 * e1;       // e9
                    qp[1] = e8 * e2;       // e10
                    qp[2] = qp[0] * e2;    // e11
                    qp[3] = e8 * e4;       // e12
                    qp[4] = qp[2] * e2;    // e13
                    qp[5] = qp[3] * e2;    // e14
                    qp[6] = qp[4] * e2;    // e15
                    qp[7] = e8 * e8;       // e16
                }

                float4 bb0 = ((const float4*)sB)[(t + q) * 4 + sh * 2 + 0];
                float4 bb1 = ((const float4*)sB)[(t + q) * 4 + sh * 2 + 1];
                float4 cc0 = ((const float4*)sC)[(t + q) * 4 + sh * 2 + 0];
                float4 cc1 = ((const float4*)sC)[(t + q) * 4 + sh * 2 + 1];
                float Bv[8] = {bb0.x, bb0.y, bb0.z, bb0.w, bb1.x, bb1.y, bb1.z, bb1.w};
                float gC[8] = {gv*cc0.x, gv*cc0.y, gv*cc0.z, gv*cc0.w,
                               gv*cc1.x, gv*cc1.y, gv*cc1.z, gv*cc1.w};

#pragma unroll
                for (int j = 0; j < 8; j++){
                    P[j] *= qp[j];
                    h[j] = fmaf(qp[j], h[j], dxv * Bv[j]);
                    accl = fmaf(h[j], gC[j], accl);
                    S[j] = fmaf(P[j], gC[j], S[j]);
                }
                if (!sh) accl = fmaf(gv * xcv, Dd, accl);   // warp-uniform branch
            }
            base = nb;
        }
    } else {
#pragma unroll 1
        for (int t = 0; t < CLEN; t++){
            float2 dxc  = g_dxc[base];
            float delta = dxc.x;
            float xcv   = dxc.y;
            float gv    = g_gate[base];
            float dxv   = delta * xcv;
#pragma unroll 4
            for (int j = 0; j < 8; j++){
                float An = -__expf(__ldg(A_log + d * 16 + n0 + j));
                float dA = __expf(delta * An);
                float Bn = sB[t * 16 + n0 + j];
                float Cn = sC[t * 16 + n0 + j] * gv;
                P[j] *= dA;
                h[j] = fmaf(dA, h[j], dxv * Bn);
                accl = fmaf(h[j], Cn, accl);
                S[j] = fmaf(P[j], Cn, S[j]);
            }
            if (!sh) accl = fmaf(gv * xcv, Dd, accl);
            base += 256;
        }
    }

    if (sh) sacc[dl] = accl;
    __syncthreads();

    const int cb = b * NCH + c;
    if (!sh) g_accl[cb * DI + d] = accl + sacc[dl];
#pragma unroll
    for (int qq = 0; qq < 2; qq++){
        int q = sh * 2 + qq;
        g_P4[(cb * 4 + q) * DI + d] = make_float4(P[qq*4+0], P[qq*4+1], P[qq*4+2], P[qq*4+3]);
        g_h4[(cb * 4 + q) * DI + d] = make_float4(h[qq*4+0], h[qq*4+1], h[qq*4+2], h[qq*4+3]);
        g_S4[(cb * 4 + q) * DI + d] = make_float4(S[qq*4+0], S[qq*4+1], S[qq*4+2], S[qq*4+3]);
    }
}

// ---------------- K5a: combine 4 chunks -> 1 segment ----------------
__global__ void __launch_bounds__(256) k5a_combine()
{
    const int b   = blockIdx.x >> 3;
    const int s   = blockIdx.x & (NSEG - 1);
    const int tid = threadIdx.x;
    const int cb0 = b * NCH + s * 4;

    float Pg[16], hg[16], Sg[16];
#pragma unroll
    for (int n = 0; n < 16; n++){ Pg[n] = 1.0f; hg[n] = 0.0f; Sg[n] = 0.0f; }
    float a = 0.0f;

    float  a2[2];
    float4 sv[2][4], pv[2][4], hv[2][4];

    a2[0] = g_accl[cb0 * DI + tid];
#pragma unroll
    for (int q = 0; q < 4; q++){
        sv[0][q] = g_S4[(cb0 * 4 + q) * DI + tid];
        pv[0][q] = g_P4[(cb0 * 4 + q) * DI + tid];
        hv[0][q] = g_h4[(cb0 * 4 + q) * DI + tid];
    }

#pragma unroll
    for (int ci = 0; ci < 4; ci++){
        const int cur = ci & 1, nxt = cur ^ 1;
        if (ci < 3){
            int cb = cb0 + ci + 1;
            a2[nxt] = g_accl[cb * DI + tid];
#pragma unroll
            for (int q = 0; q < 4; q++){
                sv[nxt][q] = g_S4[(cb * 4 + q) * DI + tid];
                pv[nxt][q] = g_P4[(cb * 4 + q) * DI + tid];
                hv[nxt][q] = g_h4[(cb * 4 + q) * DI + tid];
            }
        }
        a += a2[cur];
#pragma unroll
        for (int q = 0; q < 4; q++){
            a = fmaf(hg[q*4+0], sv[cur][q].x, a);
            a = fmaf(hg[q*4+1], sv[cur][q].y, a);
            a = fmaf(hg[q*4+2], sv[cur][q].z, a);
            a = fmaf(hg[q*4+3], sv[cur][q].w, a);
            Sg[q*4+0] = fmaf(Pg[q*4+0], sv[cur][q].x, Sg[q*4+0]);
            Sg[q*4+1] = fmaf(Pg[q*4+1], sv[cur][q].y, Sg[q*4+1]);
            Sg[q*4+2] = fmaf(Pg[q*4+2], sv[cur][q].z, Sg[q*4+2]);
            Sg[q*4+3] = fmaf(Pg[q*4+3], sv[cur][q].w, Sg[q*4+3]);
            hg[q*4+0] = fmaf(pv[cur][q].x, hg[q*4+0], hv[cur][q].x);
            hg[q*4+1] = fmaf(pv[cur][q].y, hg[q*4+1], hv[cur][q].y);
            hg[q*4+2] = fmaf(pv[cur][q].z, hg[q*4+2], hv[cur][q].z);
            hg[q*4+3] = fmaf(pv[cur][q].w, hg[q*4+3], hv[cur][q].w);
            Pg[q*4+0] *= pv[cur][q].x; Pg[q*4+1] *= pv[cur][q].y;
            Pg[q*4+2] *= pv[cur][q].z; Pg[q*4+3] *= pv[cur][q].w;
        }
    }

    const int sb = b * NSEG + s;
    g_accs[sb * DI + tid] = a;
#pragma unroll
    for (int q = 0; q < 4; q++){
        g_Ps4[(sb * 4 + q) * DI + tid] = make_float4(Pg[q*4+0], Pg[q*4+1], Pg[q*4+2], Pg[q*4+3]);
        g_hs4[(sb * 4 + q) * DI + tid] = make_float4(hg[q*4+0], hg[q*4+1], hg[q*4+2], hg[q*4+3]);
        g_Ss4[(sb * 4 + q) * DI + tid] = make_float4(Sg[q*4+0], Sg[q*4+1], Sg[q*4+2], Sg[q*4+3]);
    }
}

// ---------------- K5b: combine 8 segments + out_proj + mean + classifier ----------------
__global__ void __launch_bounds__(256) k5b_tail(const float* __restrict__ opw,
                                                const float* __restrict__ clw,
                                                const float* __restrict__ clb,
                                                float* __restrict__ out)
{
    __shared__ float sacc[256];
    __shared__ float mvec[128];
    const int b   = blockIdx.x;
    const int tid = threadIdx.x;
    const int sb0 = b * NSEG;

    float h[16];
#pragma unroll
    for (int n = 0; n < 16; n++) h[n] = 0.0f;
    float acc = 0.0f;

    float  a2[2];
    float4 sv[2][4], pv[2][4], hv[2][4];

    a2[0] = g_accs[sb0 * DI + tid];
#pragma unroll
    for (int q = 0; q < 4; q++){
        sv[0][q] = g_Ss4[(sb0 * 4 + q) * DI + tid];
        pv[0][q] = g_Ps4[(sb0 * 4 + q) * DI + tid];
        hv[0][q] = g_hs4[(sb0 * 4 + q) * DI + tid];
    }

#pragma unroll
    for (int s = 0; s < NSEG; s++){
        const int cur = s & 1, nxt = cur ^ 1;
        if (s < NSEG - 1){
            int sb = sb0 + s + 1;
            a2[nxt] = g_accs[sb * DI + tid];
#pragma unroll
            for (int q = 0; q < 4; q++){
                sv[nxt][q] = g_Ss4[(sb * 4 + q) * DI + tid];
                pv[nxt][q] = g_Ps4[(sb * 4 + q) * DI + tid];
                hv[nxt][q] = g_hs4[(sb * 4 + q) * DI + tid];
            }
        }
        acc += a2[cur];
#pragma unroll
        for (int q = 0; q < 4; q++){
            acc = fmaf(h[q*4+0], sv[cur][q].x, acc);
            acc = fmaf(h[q*4+1], sv[cur][q].y, acc);
            acc = fmaf(h[q*4+2], sv[cur][q].z, acc);
            acc = fmaf(h[q*4+3], sv[cur][q].w, acc);
            h[q*4+0] = fmaf(pv[cur][q].x, h[q*4+0], hv[cur][q].x);
            h[q*4+1] = fmaf(pv[cur][q].y, h[q*4+1], hv[cur][q].y);
            h[q*4+2] = fmaf(pv[cur][q].z, h[q*4+2], hv[cur][q].z);
            h[q*4+3] = fmaf(pv[cur][q].w, h[q*4+3], hv[cur][q].w);
        }
    }
    sacc[tid] = acc;
    __syncthreads();

    if (tid < 128){
        float s = 0.0f;
#pragma unroll 8
        for (int e = 0; e < 256; e++) s = fmaf(sacc[e], __ldg(opw + tid * 256 + e), s);
        mvec[tid] = s * (1.0f / 2048.0f);
    }
    __syncthreads();
    if (tid < 2){
        float t = __ldg(clb + tid);
#pragma unroll 8
        for (int e = 0; e < 128; e++) t = fmaf(mvec[e], __ldg(clw + tid * 128 + e), t);
        out[b * 2 + tid] = t;
    }
}

// ---------------- launch ----------------
extern "C" void kernel_launch(void* const* d_in, const int* in_sizes, int n_in,
                              void* d_out, int out_size)
{
    const int*   ids  = (const int*)  d_in[0];
    const float* emb  = (const float*)d_in[1];
    const float* ipw  = (const float*)d_in[2];
    const float* cw   = (const float*)d_in[3];
    const float* cb   = (const float*)d_in[4];
    const float* xpw  = (const float*)d_in[5];
    const float* dtw  = (const float*)d_in[6];
    const float* dtb  = (const float*)d_in[7];
    const float* alog = (const float*)d_in[8];
    const float* dvec = (const float*)d_in[9];
    const float* opw  = (const float*)d_in[10];
    const float* clw  = (const float*)d_in[11];
    const float* clb  = (const float*)d_in[12];
    float* out = (float*)d_out;

    dim3 g1(BLn / 128, 4);   // 256 m-tiles x 4 n-tiles of 128
    k1_inproj<<<g1, 256>>>(ids, emb, ipw, cw, cb);
    k3_xproj<<<BLn / TB3, 256>>>(xpw, dtw, dtb);
    k4_scan<<<Bsz * NCH * 2, 256>>>(alog, dvec);
    k5a_combine<<<Bsz * NSEG, 256>>>();
    k5b_tail<<<Bsz, 256>>>(opw, clw, clb, out);
}